// round 2
// baseline (speedup 1.0000x reference)
#include <cuda_runtime.h>
#include <cuda_bf16.h>
#include <cstdint>

#define N_NODES 50000
#define N_EDGES 800000
#define IN_DIM 256
#define OUT_DIM 256

// Scratch: aggregated features (segment_sum result), 50000 x 256 fp32 = 51.2 MB
__device__ float g_agg[(size_t)N_NODES * IN_DIM];

// ---------------------------------------------------------------------------
// Kernel 1: zero the aggregation buffer (float4 stores)
// ---------------------------------------------------------------------------
__global__ void zero_agg_kernel() {
    size_t n4 = (size_t)N_NODES * IN_DIM / 4;
    size_t i = (size_t)blockIdx.x * blockDim.x + threadIdx.x;
    float4* p = reinterpret_cast<float4*>(g_agg);
    for (; i < n4; i += (size_t)gridDim.x * blockDim.x) {
        p[i] = make_float4(0.f, 0.f, 0.f, 0.f);
    }
}

// ---------------------------------------------------------------------------
// Kernel 2: scatter-add  agg[dst] += feature[src]
// 64 threads per edge, one float4 (16B) per thread; red.global.add.v4.f32
// avoids the atomic return trip and cuts op count 4x vs scalar atomicAdd.
// ---------------------------------------------------------------------------
__device__ __forceinline__ void red_add_v4(float* addr, float4 v) {
    asm volatile("red.global.add.v4.f32 [%0], {%1, %2, %3, %4};"
                 :: "l"(addr), "f"(v.x), "f"(v.y), "f"(v.z), "f"(v.w)
                 : "memory");
}

__global__ void scatter_kernel(const float* __restrict__ feat,
                               const int* __restrict__ src,
                               const int* __restrict__ dst) {
    // work item = (edge, 16B-chunk); 64 chunks of float4 cover IN_DIM=256
    long long id = (long long)blockIdx.x * blockDim.x + threadIdx.x;
    int edge = (int)(id >> 6);
    int chunk = (int)(id & 63);
    if (edge >= N_EDGES) return;
    int s = __ldg(src + edge);   // uniform within warp -> broadcast load
    int d = __ldg(dst + edge);
    const float4* fp = reinterpret_cast<const float4*>(feat + (size_t)s * IN_DIM) + chunk;
    float4 v = __ldg(fp);
    float* ap = g_agg + (size_t)d * IN_DIM + chunk * 4;
    red_add_v4(ap, v);
}

// ---------------------------------------------------------------------------
// Kernel 3: out = agg @ W   (M=50000, K=256, N=256), fp32 register-tiled
// Block tile 64x64, BK=16, 256 threads, 4x4 outputs/thread, float4 smem reads
// ---------------------------------------------------------------------------
#define BM 64
#define BN 64
#define BK 16

__global__ __launch_bounds__(256) void gemm_kernel(const float* __restrict__ W,
                                                   float* __restrict__ out) {
    __shared__ float As[BK][BM];   // A tile transposed: As[k][m]
    __shared__ float Bs[BK][BN];   // B tile: Bs[k][n]

    const float* A = g_agg;
    int tid = threadIdx.x;
    int block_m = blockIdx.x * BM;
    int block_n = blockIdx.y * BN;

    int ty = tid >> 4;         // 0..15
    int tx = tid & 15;         // 0..15

    // load mapping
    int arow  = tid >> 2;         // 0..63
    int acol4 = (tid & 3) * 4;    // 0,4,8,12
    int brow  = tid >> 4;         // 0..15
    int bcol4 = (tid & 15) * 4;   // 0..60

    float acc[4][4];
#pragma unroll
    for (int i = 0; i < 4; i++)
#pragma unroll
        for (int j = 0; j < 4; j++) acc[i][j] = 0.f;

    for (int k0 = 0; k0 < IN_DIM; k0 += BK) {
        // A tile: 64 rows x 16 k, one float4 per thread
        float4 av = make_float4(0.f, 0.f, 0.f, 0.f);
        int gr = block_m + arow;
        if (gr < N_NODES)
            av = *reinterpret_cast<const float4*>(A + (size_t)gr * IN_DIM + k0 + acol4);
        As[acol4 + 0][arow] = av.x;
        As[acol4 + 1][arow] = av.y;
        As[acol4 + 2][arow] = av.z;
        As[acol4 + 3][arow] = av.w;

        // B tile: 16 k x 64 n, one float4 per thread
        float4 bv = *reinterpret_cast<const float4*>(
            W + (size_t)(k0 + brow) * OUT_DIM + block_n + bcol4);
        *reinterpret_cast<float4*>(&Bs[brow][bcol4]) = bv;

        __syncthreads();

#pragma unroll
        for (int k = 0; k < BK; k++) {
            float4 a = *reinterpret_cast<const float4*>(&As[k][ty * 4]);
            float4 b = *reinterpret_cast<const float4*>(&Bs[k][tx * 4]);
            float ar[4] = {a.x, a.y, a.z, a.w};
            float br[4] = {b.x, b.y, b.z, b.w};
#pragma unroll
            for (int i = 0; i < 4; i++)
#pragma unroll
                for (int j = 0; j < 4; j++)
                    acc[i][j] = fmaf(ar[i], br[j], acc[i][j]);
        }
        __syncthreads();
    }

    // store 4x4 per thread, vectorized along n
#pragma unroll
    for (int i = 0; i < 4; i++) {
        int row = block_m + ty * 4 + i;
        if (row >= N_NODES) continue;
        float4 v = make_float4(acc[i][0], acc[i][1], acc[i][2], acc[i][3]);
        *reinterpret_cast<float4*>(out + (size_t)row * OUT_DIM + block_n + tx * 4) = v;
    }
}

// ---------------------------------------------------------------------------
extern "C" void kernel_launch(void* const* d_in, const int* in_sizes, int n_in,
                              void* d_out, int out_size) {
    const float* feature = (const float*)d_in[0];
    const float* weight  = (const float*)d_in[1];
    const int*   src     = (const int*)d_in[2];
    const int*   dst     = (const int*)d_in[3];
    float* out = (float*)d_out;

    // 1) zero agg
    zero_agg_kernel<<<1024, 256>>>();

    // 2) scatter: E * 64 work items
    long long work = (long long)N_EDGES * 64;
    int sblocks = (int)((work + 255) / 256);
    scatter_kernel<<<sblocks, 256>>>(feature, src, dst);

    // 3) gemm
    dim3 ggrid((N_NODES + BM - 1) / BM, OUT_DIM / BN);
    gemm_kernel<<<ggrid, 256>>>(weight, out);
}

// round 4
// speedup vs baseline: 1.6576x; 1.6576x over previous
#include <cuda_runtime.h>
#include <cuda_bf16.h>
#include <cstdint>

#define N_NODES 50000
#define N_EDGES 800000
#define IN_DIM 256
#define OUT_DIM 256

// Scratch (device globals; no allocations allowed)
__device__ float g_agg[(size_t)N_NODES * IN_DIM];   // 51.2 MB
__device__ int   g_deg[N_NODES];
__device__ int   g_off[N_NODES + 1];
__device__ int   g_pos[N_NODES];
__device__ int   g_csr_src[N_EDGES];                // src grouped by dst

// ---------------------------------------------------------------------------
// CSR build: zero-deg -> histogram -> scan -> fill
// ---------------------------------------------------------------------------
__global__ void zero_deg_kernel() {
    int i = blockIdx.x * blockDim.x + threadIdx.x;
    if (i < N_NODES) g_deg[i] = 0;
}

__global__ void hist_kernel(const int* __restrict__ dst) {
    int e = blockIdx.x * blockDim.x + threadIdx.x;
    if (e < N_EDGES) atomicAdd(&g_deg[dst[e]], 1);
}

// single-block scan: 1024 threads, contiguous chunks + Hillis-Steele on sums
__global__ __launch_bounds__(1024) void scan_kernel() {
    __shared__ int sums[1024];
    int tid = threadIdx.x;
    const int CH = (N_NODES + 1023) / 1024;  // 49
    int start = tid * CH;
    int end = start + CH; if (end > N_NODES) end = N_NODES;
    int s = 0;
    for (int i = start; i < end; i++) s += g_deg[i];
    sums[tid] = s;
    __syncthreads();
    for (int off = 1; off < 1024; off <<= 1) {
        int v = (tid >= off) ? sums[tid - off] : 0;
        __syncthreads();
        sums[tid] += v;
        __syncthreads();
    }
    int base = (tid > 0) ? sums[tid - 1] : 0;
    for (int i = start; i < end; i++) {
        g_off[i] = base;
        g_pos[i] = base;
        base += g_deg[i];
    }
    if (tid == 1023) g_off[N_NODES] = base;
}

__global__ void fill_kernel(const int* __restrict__ src,
                            const int* __restrict__ dst) {
    int e = blockIdx.x * blockDim.x + threadIdx.x;
    if (e >= N_EDGES) return;
    int d = dst[e];
    int p = atomicAdd(&g_pos[d], 1);
    g_csr_src[p] = src[e];
}

// ---------------------------------------------------------------------------
// Gather-sum: agg[node] = sum_{e in csr[node]} feature[src[e]]
// 64 threads per node, each owns one float4 chunk. Warp = one node,
// 32 consecutive chunks -> csr_src load is a broadcast, feat loads 512B
// contiguous per warp. No atomics; each agg row written exactly once.
// ---------------------------------------------------------------------------
__global__ void gather_kernel(const float* __restrict__ feat) {
    long long id = (long long)blockIdx.x * blockDim.x + threadIdx.x;
    int node = (int)(id >> 6);
    int chunk = (int)(id & 63);
    if (node >= N_NODES) return;
    int b = g_off[node];
    int e = g_off[node + 1];
    float4 acc = make_float4(0.f, 0.f, 0.f, 0.f);
    for (int i = b; i < e; i++) {
        int s = __ldg(&g_csr_src[i]);
        float4 v = __ldg(reinterpret_cast<const float4*>(feat + (size_t)s * IN_DIM) + chunk);
        acc.x += v.x; acc.y += v.y; acc.z += v.z; acc.w += v.w;
    }
    *reinterpret_cast<float4*>(g_agg + (size_t)node * IN_DIM + chunk * 4) = acc;
}

// ---------------------------------------------------------------------------
// GEMM: out = agg @ W   (M=50000, K=256, N=256)
// 128x128 block tile, BK=8, 256 threads, 8x8 per thread -> FFMA-bound
// ---------------------------------------------------------------------------
#define BM 128
#define BN 128
#define BK 8

__global__ __launch_bounds__(256) void gemm_kernel(const float* __restrict__ W,
                                                   float* __restrict__ out) {
    __shared__ float As[BK][BM];   // transposed: As[k][m]
    __shared__ float Bs[BK][BN];

    const float* A = g_agg;
    int tid = threadIdx.x;
    int block_m = blockIdx.x * BM;
    int block_n = blockIdx.y * BN;

    int ty = tid >> 4;     // 0..15
    int tx = tid & 15;     // 0..15

    // load mapping
    int arow  = tid >> 1;          // 0..127
    int acol4 = (tid & 1) * 4;     // 0 or 4
    int brow  = tid >> 5;          // 0..7
    int bcol4 = (tid & 31) * 4;    // 0..124

    float acc[8][8];
#pragma unroll
    for (int i = 0; i < 8; i++)
#pragma unroll
        for (int j = 0; j < 8; j++) acc[i][j] = 0.f;

    for (int k0 = 0; k0 < IN_DIM; k0 += BK) {
        // A tile: 128 rows x 8 k, one float4 per thread
        float4 av = make_float4(0.f, 0.f, 0.f, 0.f);
        int gr = block_m + arow;
        if (gr < N_NODES)
            av = *reinterpret_cast<const float4*>(A + (size_t)gr * IN_DIM + k0 + acol4);
        As[acol4 + 0][arow] = av.x;
        As[acol4 + 1][arow] = av.y;
        As[acol4 + 2][arow] = av.z;
        As[acol4 + 3][arow] = av.w;

        // B tile: 8 k x 128 n, one float4 per thread
        float4 bv = *reinterpret_cast<const float4*>(
            W + (size_t)(k0 + brow) * OUT_DIM + block_n + bcol4);
        *reinterpret_cast<float4*>(&Bs[brow][bcol4]) = bv;

        __syncthreads();

#pragma unroll
        for (int k = 0; k < BK; k++) {
            float a[8], b[8];
            float4 a0 = *reinterpret_cast<const float4*>(&As[k][ty * 8]);
            float4 a1 = *reinterpret_cast<const float4*>(&As[k][ty * 8 + 4]);
            float4 b0 = *reinterpret_cast<const float4*>(&Bs[k][tx * 8]);
            float4 b1 = *reinterpret_cast<const float4*>(&Bs[k][tx * 8 + 4]);
            a[0]=a0.x; a[1]=a0.y; a[2]=a0.z; a[3]=a0.w;
            a[4]=a1.x; a[5]=a1.y; a[6]=a1.z; a[7]=a1.w;
            b[0]=b0.x; b[1]=b0.y; b[2]=b0.z; b[3]=b0.w;
            b[4]=b1.x; b[5]=b1.y; b[6]=b1.z; b[7]=b1.w;
#pragma unroll
            for (int i = 0; i < 8; i++)
#pragma unroll
                for (int j = 0; j < 8; j++)
                    acc[i][j] = fmaf(a[i], b[j], acc[i][j]);
        }
        __syncthreads();
    }

#pragma unroll
    for (int i = 0; i < 8; i++) {
        int row = block_m + ty * 8 + i;
        if (row >= N_NODES) continue;
        float4 v0 = make_float4(acc[i][0], acc[i][1], acc[i][2], acc[i][3]);
        float4 v1 = make_float4(acc[i][4], acc[i][5], acc[i][6], acc[i][7]);
        float* o = out + (size_t)row * OUT_DIM + block_n + tx * 8;
        *reinterpret_cast<float4*>(o)     = v0;
        *reinterpret_cast<float4*>(o + 4) = v1;
    }
}

// ---------------------------------------------------------------------------
extern "C" void kernel_launch(void* const* d_in, const int* in_sizes, int n_in,
                              void* d_out, int out_size) {
    const float* feature = (const float*)d_in[0];
    const float* weight  = (const float*)d_in[1];
    const int*   src     = (const int*)d_in[2];
    const int*   dst     = (const int*)d_in[3];
    float* out = (float*)d_out;

    // CSR build
    zero_deg_kernel<<<(N_NODES + 255) / 256, 256>>>();
    hist_kernel<<<(N_EDGES + 255) / 256, 256>>>(dst);
    scan_kernel<<<1, 1024>>>();
    fill_kernel<<<(N_EDGES + 255) / 256, 256>>>(src, dst);

    // Gather-sum into g_agg (writes every row; no zero pass needed)
    long long work = (long long)N_NODES * 64;
    int gblocks = (int)((work + 255) / 256);
    gather_kernel<<<gblocks, 256>>>(feature);

    // GEMM
    dim3 ggrid((N_NODES + BM - 1) / BM, OUT_DIM / BN);
    gemm_kernel<<<ggrid, 256>>>(weight, out);
}

// round 8
// speedup vs baseline: 1.9580x; 1.1812x over previous
#include <cuda_runtime.h>
#include <cuda_bf16.h>
#include <cstdint>

#define N_NODES 50000
#define N_EDGES 800000
#define IN_DIM 256
#define OUT_DIM 256
#define N_PAD 50048                 // 391 * 128

// ---------------- scratch (device globals; no allocs) ----------------
__device__ __nv_bfloat16 g_agg_hi[(size_t)N_PAD * IN_DIM];   // 25.6 MB
__device__ __nv_bfloat16 g_agg_lo[(size_t)N_PAD * IN_DIM];   // 25.6 MB
__device__ __nv_bfloat16 g_w_hi[IN_DIM * OUT_DIM];           // transposed: [n][k]
__device__ __nv_bfloat16 g_w_lo[IN_DIM * OUT_DIM];
__device__ int g_deg[N_NODES];
__device__ int g_off[N_NODES + 1];
__device__ int g_pos[N_NODES];
__device__ int g_csr_src[N_EDGES];

#define SWZ128(off) ((off) ^ (((off) >> 3) & 0x70))

__device__ __forceinline__ uint32_t smem_u32(const void* p) {
    uint32_t a;
    asm("{ .reg .u64 t; cvta.to.shared.u64 t, %1; cvt.u32.u64 %0, t; }" : "=r"(a) : "l"(p));
    return a;
}

__device__ __forceinline__ void ldmx4(uint32_t addr, uint32_t& r0, uint32_t& r1,
                                      uint32_t& r2, uint32_t& r3) {
    asm volatile("ldmatrix.sync.aligned.m8n8.x4.shared.b16 {%0,%1,%2,%3}, [%4];"
                 : "=r"(r0), "=r"(r1), "=r"(r2), "=r"(r3) : "r"(addr));
}

__device__ __forceinline__ void mma_bf16(float* c, const uint32_t* a, const uint32_t* b) {
    asm volatile(
        "mma.sync.aligned.m16n8k16.row.col.f32.bf16.bf16.f32 "
        "{%0,%1,%2,%3}, {%4,%5,%6,%7}, {%8,%9}, {%0,%1,%2,%3};"
        : "+f"(c[0]), "+f"(c[1]), "+f"(c[2]), "+f"(c[3])
        : "r"(a[0]), "r"(a[1]), "r"(a[2]), "r"(a[3]), "r"(b[0]), "r"(b[1]));
}

// ---------------------------------------------------------------------------
// CSR build
// ---------------------------------------------------------------------------
__global__ void zero_deg_kernel() {
    int i = blockIdx.x * blockDim.x + threadIdx.x;
    if (i < N_NODES) g_deg[i] = 0;
}
__global__ void hist_kernel(const int* __restrict__ dst) {
    int e = blockIdx.x * blockDim.x + threadIdx.x;
    if (e < N_EDGES) atomicAdd(&g_deg[dst[e]], 1);
}
__global__ __launch_bounds__(1024) void scan_kernel() {
    __shared__ int sums[1024];
    int tid = threadIdx.x;
    const int CH = (N_NODES + 1023) / 1024;
    int start = tid * CH;
    int end = start + CH; if (end > N_NODES) end = N_NODES;
    int s = 0;
    for (int i = start; i < end; i++) s += g_deg[i];
    sums[tid] = s;
    __syncthreads();
    for (int off = 1; off < 1024; off <<= 1) {
        int v = (tid >= off) ? sums[tid - off] : 0;
        __syncthreads();
        sums[tid] += v;
        __syncthreads();
    }
    int base = (tid > 0) ? sums[tid - 1] : 0;
    for (int i = start; i < end; i++) {
        g_off[i] = base;
        g_pos[i] = base;
        base += g_deg[i];
    }
    if (tid == 1023) g_off[N_NODES] = base;
}
__global__ void fill_kernel(const int* __restrict__ src, const int* __restrict__ dst) {
    int e = blockIdx.x * blockDim.x + threadIdx.x;
    if (e >= N_EDGES) return;
    int p = atomicAdd(&g_pos[dst[e]], 1);
    g_csr_src[p] = src[e];
}

// ---------------------------------------------------------------------------
// Gather-sum -> split bf16 hi/lo directly
// ---------------------------------------------------------------------------
__global__ void gather_kernel(const float* __restrict__ feat) {
    long long id = (long long)blockIdx.x * blockDim.x + threadIdx.x;
    int node = (int)(id >> 6);
    int chunk = (int)(id & 63);
    if (node >= N_PAD) return;

    float4 acc = make_float4(0.f, 0.f, 0.f, 0.f);
    if (node < N_NODES) {
        int b = g_off[node];
        int e = g_off[node + 1];
        for (int i = b; i < e; i++) {
            int s = __ldg(&g_csr_src[i]);
            float4 v = __ldg(reinterpret_cast<const float4*>(feat + (size_t)s * IN_DIM) + chunk);
            acc.x += v.x; acc.y += v.y; acc.z += v.z; acc.w += v.w;
        }
    }
    __nv_bfloat16 h0 = __float2bfloat16(acc.x), h1 = __float2bfloat16(acc.y);
    __nv_bfloat16 h2 = __float2bfloat16(acc.z), h3 = __float2bfloat16(acc.w);
    __nv_bfloat16 l0 = __float2bfloat16(acc.x - __bfloat162float(h0));
    __nv_bfloat16 l1 = __float2bfloat16(acc.y - __bfloat162float(h1));
    __nv_bfloat16 l2 = __float2bfloat16(acc.z - __bfloat162float(h2));
    __nv_bfloat16 l3 = __float2bfloat16(acc.w - __bfloat162float(h3));
    size_t base = (size_t)node * IN_DIM + chunk * 4;
    ushort4 hv, lv;
    hv.x = __bfloat16_as_ushort(h0); hv.y = __bfloat16_as_ushort(h1);
    hv.z = __bfloat16_as_ushort(h2); hv.w = __bfloat16_as_ushort(h3);
    lv.x = __bfloat16_as_ushort(l0); lv.y = __bfloat16_as_ushort(l1);
    lv.z = __bfloat16_as_ushort(l2); lv.w = __bfloat16_as_ushort(l3);
    *reinterpret_cast<ushort4*>(&g_agg_hi[base]) = hv;
    *reinterpret_cast<ushort4*>(&g_agg_lo[base]) = lv;
}

// ---------------------------------------------------------------------------
// Weight split + transpose: g_w_hi/lo[n][k] = split(W[k][n])
// ---------------------------------------------------------------------------
__global__ void wsplit_kernel(const float* __restrict__ W) {
    int k = blockIdx.x;
    int n = threadIdx.x;
    float x = W[(size_t)k * OUT_DIM + n];
    __nv_bfloat16 h = __float2bfloat16(x);
    __nv_bfloat16 l = __float2bfloat16(x - __bfloat162float(h));
    g_w_hi[(size_t)n * IN_DIM + k] = h;
    g_w_lo[(size_t)n * IN_DIM + k] = l;
}

// ---------------------------------------------------------------------------
// HMMA GEMM: out[m,n] = (Ahi+Alo)[m,k] @ (Bhi+Blo)[n,k]^T, 3-MMA bf16 split
// Block 128x128, 8 warps (2m x 4n), warp tile 64x32, K chunk 64, SW128 smem.
// ---------------------------------------------------------------------------
#define KC 64
#define SA_HI 0
#define SA_LO 16384
#define SB_HI 32768
#define SB_LO 49152
#define SMEM_GEMM 65536

__global__ __launch_bounds__(256, 1) void mma_gemm_kernel(float* __restrict__ out) {
    extern __shared__ char smem[];
    uint32_t sb = smem_u32(smem);
    int tid = threadIdx.x;
    int wid = tid >> 5;
    int lid = tid & 31;
    size_t block_m = (size_t)blockIdx.x * 128;
    int block_n = blockIdx.y * 128;

    int wm = (wid >> 2) * 64;     // warp m offset: 0 or 64
    int wn = (wid & 3) * 32;      // warp n offset: 0,32,64,96

    const uint4* ahi = reinterpret_cast<const uint4*>(g_agg_hi);
    const uint4* alo = reinterpret_cast<const uint4*>(g_agg_lo);
    const uint4* bhi = reinterpret_cast<const uint4*>(g_w_hi);
    const uint4* blo = reinterpret_cast<const uint4*>(g_w_lo);

    float acc[4][4][4];
#pragma unroll
    for (int i = 0; i < 4; i++)
#pragma unroll
        for (int j = 0; j < 4; j++)
#pragma unroll
            for (int q = 0; q < 4; q++) acc[i][j][q] = 0.f;

    // per-lane ldmatrix base offsets (within a chunk tile, 128B rows)
    int a_row = wm + (lid & 15);
    int a_kb  = (lid >> 4) * 16;           // 0 or 16 bytes (k 0..7 / 8..15)
    int bq    = lid >> 3;                  // quarter 0..3
    int b_row_off = (bq >> 1) * 8 + (lid & 7);
    int b_kb  = (bq & 1) * 16;

    for (int c = 0; c < 4; c++) {
        int k0 = c * KC;
        // load A tiles: 128 rows x 8 uint4/row, hi+lo
        for (int idx = tid; idx < 1024; idx += 256) {
            int row = idx >> 3, q = idx & 7;
            size_t gsrc = ((block_m + row) * IN_DIM + k0) / 8 + q;
            uint32_t doff = SWZ128((uint32_t)(row * 128 + q * 16));
            *reinterpret_cast<uint4*>(smem + SA_HI + doff) = __ldg(ahi + gsrc);
            *reinterpret_cast<uint4*>(smem + SA_LO + doff) = __ldg(alo + gsrc);
        }
        // load B tiles: 128 n-rows x 8 uint4/row, hi+lo
        for (int idx = tid; idx < 1024; idx += 256) {
            int row = idx >> 3, q = idx & 7;
            size_t gsrc = ((size_t)(block_n + row) * IN_DIM + k0) / 8 + q;
            uint32_t doff = SWZ128((uint32_t)(row * 128 + q * 16));
            *reinterpret_cast<uint4*>(smem + SB_HI + doff) = __ldg(bhi + gsrc);
            *reinterpret_cast<uint4*>(smem + SB_LO + doff) = __ldg(blo + gsrc);
        }
        __syncthreads();

#pragma unroll
        for (int k16 = 0; k16 < 4; k16++) {
            uint32_t a_h[4][4], a_l[4][4];
#pragma unroll
            for (int mi = 0; mi < 4; mi++) {
                uint32_t off = SWZ128((uint32_t)((a_row + mi * 16) * 128 + k16 * 32 + a_kb));
                ldmx4(sb + SA_HI + off, a_h[mi][0], a_h[mi][1], a_h[mi][2], a_h[mi][3]);
                ldmx4(sb + SA_LO + off, a_l[mi][0], a_l[mi][1], a_l[mi][2], a_l[mi][3]);
            }
            uint32_t b_h[4][2], b_l[4][2];
#pragma unroll
            for (int p = 0; p < 2; p++) {
                uint32_t off = SWZ128((uint32_t)((wn + p * 16 + b_row_off) * 128 + k16 * 32 + b_kb));
                uint32_t r0, r1, r2, r3;
                ldmx4(sb + SB_HI + off, r0, r1, r2, r3);
                b_h[p * 2][0] = r0; b_h[p * 2][1] = r1;
                b_h[p * 2 + 1][0] = r2; b_h[p * 2 + 1][1] = r3;
                ldmx4(sb + SB_LO + off, r0, r1, r2, r3);
                b_l[p * 2][0] = r0; b_l[p * 2][1] = r1;
                b_l[p * 2 + 1][0] = r2; b_l[p * 2 + 1][1] = r3;
            }
#pragma unroll
            for (int mi = 0; mi < 4; mi++)
#pragma unroll
                for (int ni = 0; ni < 4; ni++) {
                    mma_bf16(acc[mi][ni], a_h[mi], b_h[ni]);
                    mma_bf16(acc[mi][ni], a_h[mi], b_l[ni]);
                    mma_bf16(acc[mi][ni], a_l[mi], b_h[ni]);
                }
        }
        __syncthreads();
    }

    // epilogue: c fragment mapping m16n8: c0,c1 -> row=g, col=2t{+1}; c2,c3 -> row=g+8
    int g = lid >> 2;
    int t = lid & 3;
#pragma unroll
    for (int mi = 0; mi < 4; mi++) {
        size_t r0 = block_m + wm + mi * 16 + g;
        size_t r1 = r0 + 8;
#pragma unroll
        for (int ni = 0; ni < 4; ni++) {
            int col = block_n + wn + ni * 8 + t * 2;
            if (r0 < N_NODES)
                *reinterpret_cast<float2*>(out + r0 * OUT_DIM + col) =
                    make_float2(acc[mi][ni][0], acc[mi][ni][1]);
            if (r1 < N_NODES)
                *reinterpret_cast<float2*>(out + r1 * OUT_DIM + col) =
                    make_float2(acc[mi][ni][2], acc[mi][ni][3]);
        }
    }
}

// ---------------------------------------------------------------------------
extern "C" void kernel_launch(void* const* d_in, const int* in_sizes, int n_in,
                              void* d_out, int out_size) {
    const float* feature = (const float*)d_in[0];
    const float* weight  = (const float*)d_in[1];
    const int*   src     = (const int*)d_in[2];
    const int*   dst     = (const int*)d_in[3];
    float* out = (float*)d_out;

    cudaFuncSetAttribute(mma_gemm_kernel,
                         cudaFuncAttributeMaxDynamicSharedMemorySize, SMEM_GEMM);

    // CSR build
    zero_deg_kernel<<<(N_NODES + 255) / 256, 256>>>();
    hist_kernel<<<(N_EDGES + 255) / 256, 256>>>(dst);
    scan_kernel<<<1, 1024>>>();
    fill_kernel<<<(N_EDGES + 255) / 256, 256>>>(src, dst);

    // Weight split
    wsplit_kernel<<<IN_DIM, OUT_DIM>>>(weight);

    // Gather-sum -> bf16 hi/lo
    long long work = (long long)N_PAD * 64;
    gather_kernel<<<(int)((work + 255) / 256), 256>>>(feature);

    // Tensor-core GEMM (HMMA mma.sync)
    dim3 ggrid(N_PAD / 128, OUT_DIM / 128);
    mma_gemm_kernel<<<ggrid, 256, SMEM_GEMM>>>(out);
}

// round 9
// speedup vs baseline: 2.4932x; 1.2733x over previous
#include <cuda_runtime.h>
#include <cuda_bf16.h>
#include <cstdint>

#define N_NODES 50000
#define N_EDGES 800000
#define IN_DIM 256
#define OUT_DIM 256
#define N_PAD 50048                 // 391 * 128

// ---------------- scratch (device globals; no allocs) ----------------
__device__ __nv_bfloat16 g_agg_hi[(size_t)N_PAD * IN_DIM];   // 25.6 MB
__device__ __nv_bfloat16 g_agg_lo[(size_t)N_PAD * IN_DIM];   // 25.6 MB
__device__ __nv_bfloat16 g_w_hi[IN_DIM * OUT_DIM];           // transposed: [n][k]
__device__ __nv_bfloat16 g_w_lo[IN_DIM * OUT_DIM];
__device__ int g_deg[N_NODES];
__device__ int g_off[N_NODES + 1];
__device__ int g_pos[N_NODES];
__device__ int g_csr_src[N_EDGES];

#define SWZ128(off) ((off) ^ (((off) >> 3) & 0x70))

__device__ __forceinline__ uint32_t smem_u32(const void* p) {
    uint32_t a;
    asm("{ .reg .u64 t; cvta.to.shared.u64 t, %1; cvt.u32.u64 %0, t; }" : "=r"(a) : "l"(p));
    return a;
}

__device__ __forceinline__ void ldmx4(uint32_t addr, uint32_t& r0, uint32_t& r1,
                                      uint32_t& r2, uint32_t& r3) {
    asm volatile("ldmatrix.sync.aligned.m8n8.x4.shared.b16 {%0,%1,%2,%3}, [%4];"
                 : "=r"(r0), "=r"(r1), "=r"(r2), "=r"(r3) : "r"(addr));
}

__device__ __forceinline__ void mma_bf16(float* c, const uint32_t* a, const uint32_t* b) {
    asm volatile(
        "mma.sync.aligned.m16n8k16.row.col.f32.bf16.bf16.f32 "
        "{%0,%1,%2,%3}, {%4,%5,%6,%7}, {%8,%9}, {%0,%1,%2,%3};"
        : "+f"(c[0]), "+f"(c[1]), "+f"(c[2]), "+f"(c[3])
        : "r"(a[0]), "r"(a[1]), "r"(a[2]), "r"(a[3]), "r"(b[0]), "r"(b[1]));
}

__device__ __forceinline__ void cp_async16(uint32_t s, const void* g) {
    asm volatile("cp.async.cg.shared.global [%0], [%1], 16;" :: "r"(s), "l"(g));
}
#define CP_COMMIT() asm volatile("cp.async.commit_group;" ::: "memory")
#define CP_WAIT(n)  asm volatile("cp.async.wait_group %0;" :: "n"(n) : "memory")

// ---------------------------------------------------------------------------
// CSR build
// ---------------------------------------------------------------------------
__global__ void zero_deg_kernel() {
    int i = blockIdx.x * blockDim.x + threadIdx.x;
    if (i < N_NODES) g_deg[i] = 0;
}
__global__ void hist_kernel(const int* __restrict__ dst) {
    int e = blockIdx.x * blockDim.x + threadIdx.x;
    if (e < N_EDGES) atomicAdd(&g_deg[dst[e]], 1);
}
__global__ __launch_bounds__(1024) void scan_kernel() {
    __shared__ int sums[1024];
    int tid = threadIdx.x;
    const int CH = (N_NODES + 1023) / 1024;
    int start = tid * CH;
    int end = start + CH; if (end > N_NODES) end = N_NODES;
    int s = 0;
    for (int i = start; i < end; i++) s += g_deg[i];
    sums[tid] = s;
    __syncthreads();
    for (int off = 1; off < 1024; off <<= 1) {
        int v = (tid >= off) ? sums[tid - off] : 0;
        __syncthreads();
        sums[tid] += v;
        __syncthreads();
    }
    int base = (tid > 0) ? sums[tid - 1] : 0;
    for (int i = start; i < end; i++) {
        g_off[i] = base;
        g_pos[i] = base;
        base += g_deg[i];
    }
    if (tid == 1023) g_off[N_NODES] = base;
}
__global__ void fill_kernel(const int* __restrict__ src, const int* __restrict__ dst) {
    int e = blockIdx.x * blockDim.x + threadIdx.x;
    if (e >= N_EDGES) return;
    int p = atomicAdd(&g_pos[dst[e]], 1);
    g_csr_src[p] = src[e];
}

// ---------------------------------------------------------------------------
// Gather-sum -> split bf16 hi/lo directly
// ---------------------------------------------------------------------------
__global__ void gather_kernel(const float* __restrict__ feat) {
    long long id = (long long)blockIdx.x * blockDim.x + threadIdx.x;
    int node = (int)(id >> 6);
    int chunk = (int)(id & 63);
    if (node >= N_PAD) return;

    float4 acc = make_float4(0.f, 0.f, 0.f, 0.f);
    if (node < N_NODES) {
        int b = g_off[node];
        int e = g_off[node + 1];
        for (int i = b; i < e; i++) {
            int s = __ldg(&g_csr_src[i]);
            float4 v = __ldg(reinterpret_cast<const float4*>(feat + (size_t)s * IN_DIM) + chunk);
            acc.x += v.x; acc.y += v.y; acc.z += v.z; acc.w += v.w;
        }
    }
    __nv_bfloat16 h0 = __float2bfloat16(acc.x), h1 = __float2bfloat16(acc.y);
    __nv_bfloat16 h2 = __float2bfloat16(acc.z), h3 = __float2bfloat16(acc.w);
    __nv_bfloat16 l0 = __float2bfloat16(acc.x - __bfloat162float(h0));
    __nv_bfloat16 l1 = __float2bfloat16(acc.y - __bfloat162float(h1));
    __nv_bfloat16 l2 = __float2bfloat16(acc.z - __bfloat162float(h2));
    __nv_bfloat16 l3 = __float2bfloat16(acc.w - __bfloat162float(h3));
    size_t base = (size_t)node * IN_DIM + chunk * 4;
    ushort4 hv, lv;
    hv.x = __bfloat16_as_ushort(h0); hv.y = __bfloat16_as_ushort(h1);
    hv.z = __bfloat16_as_ushort(h2); hv.w = __bfloat16_as_ushort(h3);
    lv.x = __bfloat16_as_ushort(l0); lv.y = __bfloat16_as_ushort(l1);
    lv.z = __bfloat16_as_ushort(l2); lv.w = __bfloat16_as_ushort(l3);
    *reinterpret_cast<ushort4*>(&g_agg_hi[base]) = hv;
    *reinterpret_cast<ushort4*>(&g_agg_lo[base]) = lv;
}

// ---------------------------------------------------------------------------
// Weight split + transpose: g_w_hi/lo[n][k] = split(W[k][n])
// ---------------------------------------------------------------------------
__global__ void wsplit_kernel(const float* __restrict__ W) {
    int k = blockIdx.x;
    int n = threadIdx.x;
    float x = W[(size_t)k * OUT_DIM + n];
    __nv_bfloat16 h = __float2bfloat16(x);
    __nv_bfloat16 l = __float2bfloat16(x - __bfloat162float(h));
    g_w_hi[(size_t)n * IN_DIM + k] = h;
    g_w_lo[(size_t)n * IN_DIM + k] = l;
}

// ---------------------------------------------------------------------------
// HMMA GEMM with cp.async double-buffered pipeline.
// out[m,n] = (Ahi+Alo)[m,k] @ (Bhi+Blo)[n,k]^T, 3-MMA bf16 split.
// Block 128x128, 8 warps (2m x 4n), warp tile 64x32, K chunk 64, SW128 smem.
// 2 stages x 64KB = 128KB dynamic smem.
// ---------------------------------------------------------------------------
#define KC 64
#define SA_HI 0
#define SA_LO 16384
#define SB_HI 32768
#define SB_LO 49152
#define STAGE_BYTES 65536
#define SMEM_GEMM (2 * STAGE_BYTES)

__global__ __launch_bounds__(256, 1) void mma_gemm_kernel(float* __restrict__ out) {
    extern __shared__ char smem[];
    uint32_t sb = smem_u32(smem);
    int tid = threadIdx.x;
    int wid = tid >> 5;
    int lid = tid & 31;
    size_t block_m = (size_t)blockIdx.x * 128;
    int block_n = blockIdx.y * 128;

    int wm = (wid >> 2) * 64;     // warp m offset: 0 or 64
    int wn = (wid & 3) * 32;      // warp n offset: 0,32,64,96

    const char* ahi = reinterpret_cast<const char*>(g_agg_hi);
    const char* alo = reinterpret_cast<const char*>(g_agg_lo);
    const char* bhi = reinterpret_cast<const char*>(g_w_hi);
    const char* blo = reinterpret_cast<const char*>(g_w_lo);

    float acc[4][4][4];
#pragma unroll
    for (int i = 0; i < 4; i++)
#pragma unroll
        for (int j = 0; j < 4; j++)
#pragma unroll
            for (int q = 0; q < 4; q++) acc[i][j][q] = 0.f;

    // per-lane ldmatrix base offsets (within a chunk tile, 128B rows)
    int a_row = wm + (lid & 15);
    int a_kb  = (lid >> 4) * 16;           // 0 or 16 bytes (k 0..7 / 8..15)
    int bq    = lid >> 3;                  // quarter 0..3
    int b_row_off = (bq >> 1) * 8 + (lid & 7);
    int b_kb  = (bq & 1) * 16;

    // issue async loads for chunk c into stage st
    auto load_chunk = [&](int c, int st) {
        int k0 = c * KC;
        uint32_t base = sb + st * STAGE_BYTES;
#pragma unroll
        for (int it = 0; it < 4; it++) {
            int idx = tid + it * 256;          // 0..1023
            int row = idx >> 3, q = idx & 7;
            uint32_t doff = SWZ128((uint32_t)(row * 128 + q * 16));
            size_t ab = (((block_m + row) * IN_DIM + k0) << 1) + (q << 4);
            cp_async16(base + SA_HI + doff, ahi + ab);
            cp_async16(base + SA_LO + doff, alo + ab);
            size_t bb = ((((size_t)(block_n + row)) * IN_DIM + k0) << 1) + (q << 4);
            cp_async16(base + SB_HI + doff, bhi + bb);
            cp_async16(base + SB_LO + doff, blo + bb);
        }
        CP_COMMIT();
    };

    load_chunk(0, 0);

    for (int c = 0; c < 4; c++) {
        if (c < 3) {
            load_chunk(c + 1, (c + 1) & 1);   // stage buffer freed by sync at end of c-1
            CP_WAIT(1);                        // chunk c's group complete
        } else {
            CP_WAIT(0);
        }
        __syncthreads();

        uint32_t st = sb + (c & 1) * STAGE_BYTES;
#pragma unroll
        for (int k16 = 0; k16 < 4; k16++) {
            uint32_t a_h[4][4], a_l[4][4];
#pragma unroll
            for (int mi = 0; mi < 4; mi++) {
                uint32_t off = SWZ128((uint32_t)((a_row + mi * 16) * 128 + k16 * 32 + a_kb));
                ldmx4(st + SA_HI + off, a_h[mi][0], a_h[mi][1], a_h[mi][2], a_h[mi][3]);
                ldmx4(st + SA_LO + off, a_l[mi][0], a_l[mi][1], a_l[mi][2], a_l[mi][3]);
            }
            uint32_t b_h[4][2], b_l[4][2];
#pragma unroll
            for (int p = 0; p < 2; p++) {
                uint32_t off = SWZ128((uint32_t)((wn + p * 16 + b_row_off) * 128 + k16 * 32 + b_kb));
                uint32_t r0, r1, r2, r3;
                ldmx4(st + SB_HI + off, r0, r1, r2, r3);
                b_h[p * 2][0] = r0; b_h[p * 2][1] = r1;
                b_h[p * 2 + 1][0] = r2; b_h[p * 2 + 1][1] = r3;
                ldmx4(st + SB_LO + off, r0, r1, r2, r3);
                b_l[p * 2][0] = r0; b_l[p * 2][1] = r1;
                b_l[p * 2 + 1][0] = r2; b_l[p * 2 + 1][1] = r3;
            }
#pragma unroll
            for (int mi = 0; mi < 4; mi++)
#pragma unroll
                for (int ni = 0; ni < 4; ni++) {
                    mma_bf16(acc[mi][ni], a_h[mi], b_h[ni]);
                    mma_bf16(acc[mi][ni], a_h[mi], b_l[ni]);
                    mma_bf16(acc[mi][ni], a_l[mi], b_h[ni]);
                }
        }
        __syncthreads();
    }

    // epilogue: c fragment mapping m16n8: c0,c1 -> row=g, col=2t{+1}; c2,c3 -> row=g+8
    int g = lid >> 2;
    int t = lid & 3;
#pragma unroll
    for (int mi = 0; mi < 4; mi++) {
        size_t r0 = block_m + wm + mi * 16 + g;
        size_t r1 = r0 + 8;
#pragma unroll
        for (int ni = 0; ni < 4; ni++) {
            int col = block_n + wn + ni * 8 + t * 2;
            if (r0 < N_NODES)
                *reinterpret_cast<float2*>(out + r0 * OUT_DIM + col) =
                    make_float2(acc[mi][ni][0], acc[mi][ni][1]);
            if (r1 < N_NODES)
                *reinterpret_cast<float2*>(out + r1 * OUT_DIM + col) =
                    make_float2(acc[mi][ni][2], acc[mi][ni][3]);
        }
    }
}

// ---------------------------------------------------------------------------
extern "C" void kernel_launch(void* const* d_in, const int* in_sizes, int n_in,
                              void* d_out, int out_size) {
    const float* feature = (const float*)d_in[0];
    const float* weight  = (const float*)d_in[1];
    const int*   src     = (const int*)d_in[2];
    const int*   dst     = (const int*)d_in[3];
    float* out = (float*)d_out;

    cudaFuncSetAttribute(mma_gemm_kernel,
                         cudaFuncAttributeMaxDynamicSharedMemorySize, SMEM_GEMM);

    // CSR build
    zero_deg_kernel<<<(N_NODES + 255) / 256, 256>>>();
    hist_kernel<<<(N_EDGES + 255) / 256, 256>>>(dst);
    scan_kernel<<<1, 1024>>>();
    fill_kernel<<<(N_EDGES + 255) / 256, 256>>>(src, dst);

    // Weight split
    wsplit_kernel<<<IN_DIM, OUT_DIM>>>(weight);

    // Gather-sum -> bf16 hi/lo
    long long work = (long long)N_PAD * 64;
    gather_kernel<<<(int)((work + 255) / 256), 256>>>(feature);

    // Tensor-core GEMM (HMMA mma.sync, cp.async pipelined)
    dim3 ggrid(N_PAD / 128, OUT_DIM / 128);
    mma_gemm_kernel<<<ggrid, 256, SMEM_GEMM>>>(out);
}

// round 10
// speedup vs baseline: 2.5222x; 1.0116x over previous
#include <cuda_runtime.h>
#include <cuda_bf16.h>
#include <cstdint>

#define N_NODES 50000
#define N_EDGES 800000
#define IN_DIM 256
#define OUT_DIM 256
#define N_PAD 50048                 // 391 * 128

// ---------------- scratch (device globals; no allocs) ----------------
__device__ __nv_bfloat16 g_agg_hi[(size_t)N_PAD * IN_DIM];   // 25.6 MB
__device__ __nv_bfloat16 g_agg_lo[(size_t)N_PAD * IN_DIM];   // 25.6 MB
__device__ __nv_bfloat16 g_w_hi[IN_DIM * OUT_DIM];           // transposed: [n][k]
__device__ __nv_bfloat16 g_w_lo[IN_DIM * OUT_DIM];
__device__ int g_deg[N_NODES];
__device__ int g_off[N_NODES + 1];
__device__ int g_pos[N_NODES];
__device__ int g_csr_src[N_EDGES];

#define SWZ128(off) ((off) ^ (((off) >> 3) & 0x70))

__device__ __forceinline__ uint32_t smem_u32(const void* p) {
    uint32_t a;
    asm("{ .reg .u64 t; cvta.to.shared.u64 t, %1; cvt.u32.u64 %0, t; }" : "=r"(a) : "l"(p));
    return a;
}

__device__ __forceinline__ void ldmx4(uint32_t addr, uint32_t& r0, uint32_t& r1,
                                      uint32_t& r2, uint32_t& r3) {
    asm volatile("ldmatrix.sync.aligned.m8n8.x4.shared.b16 {%0,%1,%2,%3}, [%4];"
                 : "=r"(r0), "=r"(r1), "=r"(r2), "=r"(r3) : "r"(addr));
}

__device__ __forceinline__ void mma_bf16(float* c, const uint32_t* a, const uint32_t* b) {
    asm volatile(
        "mma.sync.aligned.m16n8k16.row.col.f32.bf16.bf16.f32 "
        "{%0,%1,%2,%3}, {%4,%5,%6,%7}, {%8,%9}, {%0,%1,%2,%3};"
        : "+f"(c[0]), "+f"(c[1]), "+f"(c[2]), "+f"(c[3])
        : "r"(a[0]), "r"(a[1]), "r"(a[2]), "r"(a[3]), "r"(b[0]), "r"(b[1]));
}

__device__ __forceinline__ void cp_async16(uint32_t s, const void* g) {
    asm volatile("cp.async.cg.shared.global [%0], [%1], 16;" :: "r"(s), "l"(g));
}
#define CP_COMMIT() asm volatile("cp.async.commit_group;" ::: "memory")
#define CP_WAIT(n)  asm volatile("cp.async.wait_group %0;" :: "n"(n) : "memory")

// ---------------------------------------------------------------------------
// CSR build
// ---------------------------------------------------------------------------
__global__ void zero_deg_kernel() {
    int i = blockIdx.x * blockDim.x + threadIdx.x;
    if (i < N_NODES) g_deg[i] = 0;
}
__global__ void hist_kernel(const int* __restrict__ dst) {
    int e = blockIdx.x * blockDim.x + threadIdx.x;
    if (e < N_EDGES) atomicAdd(&g_deg[dst[e]], 1);
}
__global__ __launch_bounds__(1024) void scan_kernel() {
    __shared__ int sums[1024];
    int tid = threadIdx.x;
    const int CH = (N_NODES + 1023) / 1024;
    int start = tid * CH;
    int end = start + CH; if (end > N_NODES) end = N_NODES;
    int s = 0;
    for (int i = start; i < end; i++) s += g_deg[i];
    sums[tid] = s;
    __syncthreads();
    for (int off = 1; off < 1024; off <<= 1) {
        int v = (tid >= off) ? sums[tid - off] : 0;
        __syncthreads();
        sums[tid] += v;
        __syncthreads();
    }
    int base = (tid > 0) ? sums[tid - 1] : 0;
    for (int i = start; i < end; i++) {
        g_off[i] = base;
        g_pos[i] = base;
        base += g_deg[i];
    }
    if (tid == 1023) g_off[N_NODES] = base;
}
__global__ void fill_kernel(const int* __restrict__ src, const int* __restrict__ dst) {
    int e = blockIdx.x * blockDim.x + threadIdx.x;
    if (e >= N_EDGES) return;
    int p = atomicAdd(&g_pos[dst[e]], 1);
    g_csr_src[p] = src[e];
}

// ---------------------------------------------------------------------------
// Gather-sum -> split bf16 hi/lo.  32 threads/node, 2 float4 chunks/thread,
// edge loop unrolled x4 with index prefetch (MLP ~8 per thread).
// ---------------------------------------------------------------------------
__device__ __forceinline__ void f4add(float4& a, float4 v) {
    a.x += v.x; a.y += v.y; a.z += v.z; a.w += v.w;
}

__global__ void gather_kernel(const float* __restrict__ feat) {
    long long id = (long long)blockIdx.x * blockDim.x + threadIdx.x;
    int node = (int)(id >> 5);
    int chunk = (int)(id & 31);            // float4 chunk; also owns chunk+32
    if (node >= N_PAD) return;

    float4 acc0 = make_float4(0.f, 0.f, 0.f, 0.f);
    float4 acc1 = make_float4(0.f, 0.f, 0.f, 0.f);
    if (node < N_NODES) {
        int b = g_off[node];
        int e = g_off[node + 1];
        int i = b;
        for (; i + 4 <= e; i += 4) {
            int s0 = __ldg(&g_csr_src[i]);
            int s1 = __ldg(&g_csr_src[i + 1]);
            int s2 = __ldg(&g_csr_src[i + 2]);
            int s3 = __ldg(&g_csr_src[i + 3]);
            const float4* p0 = reinterpret_cast<const float4*>(feat + (size_t)s0 * IN_DIM) + chunk;
            const float4* p1 = reinterpret_cast<const float4*>(feat + (size_t)s1 * IN_DIM) + chunk;
            const float4* p2 = reinterpret_cast<const float4*>(feat + (size_t)s2 * IN_DIM) + chunk;
            const float4* p3 = reinterpret_cast<const float4*>(feat + (size_t)s3 * IN_DIM) + chunk;
            float4 a0 = __ldg(p0), b0 = __ldg(p0 + 32);
            float4 a1 = __ldg(p1), b1 = __ldg(p1 + 32);
            float4 a2 = __ldg(p2), b2 = __ldg(p2 + 32);
            float4 a3 = __ldg(p3), b3 = __ldg(p3 + 32);
            f4add(acc0, a0); f4add(acc1, b0);
            f4add(acc0, a1); f4add(acc1, b1);
            f4add(acc0, a2); f4add(acc1, b2);
            f4add(acc0, a3); f4add(acc1, b3);
        }
        for (; i < e; i++) {
            int s = __ldg(&g_csr_src[i]);
            const float4* p = reinterpret_cast<const float4*>(feat + (size_t)s * IN_DIM) + chunk;
            f4add(acc0, __ldg(p));
            f4add(acc1, __ldg(p + 32));
        }
    }

    size_t base = (size_t)node * IN_DIM;
#pragma unroll
    for (int half = 0; half < 2; half++) {
        float4 acc = half ? acc1 : acc0;
        int ck = chunk + half * 32;
        __nv_bfloat16 h0 = __float2bfloat16(acc.x), h1 = __float2bfloat16(acc.y);
        __nv_bfloat16 h2 = __float2bfloat16(acc.z), h3 = __float2bfloat16(acc.w);
        __nv_bfloat16 l0 = __float2bfloat16(acc.x - __bfloat162float(h0));
        __nv_bfloat16 l1 = __float2bfloat16(acc.y - __bfloat162float(h1));
        __nv_bfloat16 l2 = __float2bfloat16(acc.z - __bfloat162float(h2));
        __nv_bfloat16 l3 = __float2bfloat16(acc.w - __bfloat162float(h3));
        ushort4 hv, lv;
        hv.x = __bfloat16_as_ushort(h0); hv.y = __bfloat16_as_ushort(h1);
        hv.z = __bfloat16_as_ushort(h2); hv.w = __bfloat16_as_ushort(h3);
        lv.x = __bfloat16_as_ushort(l0); lv.y = __bfloat16_as_ushort(l1);
        lv.z = __bfloat16_as_ushort(l2); lv.w = __bfloat16_as_ushort(l3);
        *reinterpret_cast<ushort4*>(&g_agg_hi[base + ck * 4]) = hv;
        *reinterpret_cast<ushort4*>(&g_agg_lo[base + ck * 4]) = lv;
    }
}

// ---------------------------------------------------------------------------
// Weight split + transpose: g_w_hi/lo[n][k] = split(W[k][n])
// ---------------------------------------------------------------------------
__global__ void wsplit_kernel(const float* __restrict__ W) {
    int k = blockIdx.x;
    int n = threadIdx.x;
    float x = W[(size_t)k * OUT_DIM + n];
    __nv_bfloat16 h = __float2bfloat16(x);
    __nv_bfloat16 l = __float2bfloat16(x - __bfloat162float(h));
    g_w_hi[(size_t)n * IN_DIM + k] = h;
    g_w_lo[(size_t)n * IN_DIM + k] = l;
}

// ---------------------------------------------------------------------------
// HMMA GEMM with cp.async 3-stage pipeline.
// out[m,n] = (Ahi+Alo)[m,k] @ (Bhi+Blo)[n,k]^T, 3-MMA bf16 split.
// Block 128x128, 8 warps (2m x 4n), warp tile 64x32, K chunk 64, SW128 smem.
// 3 stages x 64KB = 192KB dynamic smem.
// ---------------------------------------------------------------------------
#define KC 64
#define SA_HI 0
#define SA_LO 16384
#define SB_HI 32768
#define SB_LO 49152
#define STAGE_BYTES 65536
#define NSTAGE 3
#define SMEM_GEMM (NSTAGE * STAGE_BYTES)

__global__ __launch_bounds__(256, 1) void mma_gemm_kernel(float* __restrict__ out) {
    extern __shared__ char smem[];
    uint32_t sb = smem_u32(smem);
    int tid = threadIdx.x;
    int wid = tid >> 5;
    int lid = tid & 31;
    size_t block_m = (size_t)blockIdx.x * 128;
    int block_n = blockIdx.y * 128;

    int wm = (wid >> 2) * 64;     // warp m offset: 0 or 64
    int wn = (wid & 3) * 32;      // warp n offset: 0,32,64,96

    const char* ahi = reinterpret_cast<const char*>(g_agg_hi);
    const char* alo = reinterpret_cast<const char*>(g_agg_lo);
    const char* bhi = reinterpret_cast<const char*>(g_w_hi);
    const char* blo = reinterpret_cast<const char*>(g_w_lo);

    float acc[4][4][4];
#pragma unroll
    for (int i = 0; i < 4; i++)
#pragma unroll
        for (int j = 0; j < 4; j++)
#pragma unroll
            for (int q = 0; q < 4; q++) acc[i][j][q] = 0.f;

    // per-lane ldmatrix base offsets (within a chunk tile, 128B rows)
    int a_row = wm + (lid & 15);
    int a_kb  = (lid >> 4) * 16;           // 0 or 16 bytes (k 0..7 / 8..15)
    int bq    = lid >> 3;                  // quarter 0..3
    int b_row_off = (bq >> 1) * 8 + (lid & 7);
    int b_kb  = (bq & 1) * 16;

    auto load_chunk = [&](int c, int st) {
        int k0 = c * KC;
        uint32_t base = sb + st * STAGE_BYTES;
#pragma unroll
        for (int it = 0; it < 4; it++) {
            int idx = tid + it * 256;          // 0..1023
            int row = idx >> 3, q = idx & 7;
            uint32_t doff = SWZ128((uint32_t)(row * 128 + q * 16));
            size_t ab = (((block_m + row) * IN_DIM + k0) << 1) + (q << 4);
            cp_async16(base + SA_HI + doff, ahi + ab);
            cp_async16(base + SA_LO + doff, alo + ab);
            size_t bb = ((((size_t)(block_n + row)) * IN_DIM + k0) << 1) + (q << 4);
            cp_async16(base + SB_HI + doff, bhi + bb);
            cp_async16(base + SB_LO + doff, blo + bb);
        }
        CP_COMMIT();
    };

    load_chunk(0, 0);
    load_chunk(1, 1);

    for (int c = 0; c < 4; c++) {
        if (c < 2) {
            load_chunk(c + 2, (c + 2) % NSTAGE);
            CP_WAIT(2);          // chunk c complete (c+1, c+2 may remain in flight)
        } else if (c == 2) {
            CP_WAIT(1);
        } else {
            CP_WAIT(0);
        }
        __syncthreads();

        uint32_t st = sb + (c % NSTAGE) * STAGE_BYTES;
#pragma unroll
        for (int k16 = 0; k16 < 4; k16++) {
            uint32_t a_h[4][4], a_l[4][4];
#pragma unroll
            for (int mi = 0; mi < 4; mi++) {
                uint32_t off = SWZ128((uint32_t)((a_row + mi * 16) * 128 + k16 * 32 + a_kb));
                ldmx4(st + SA_HI + off, a_h[mi][0], a_h[mi][1], a_h[mi][2], a_h[mi][3]);
                ldmx4(st + SA_LO + off, a_l[mi][0], a_l[mi][1], a_l[mi][2], a_l[mi][3]);
            }
            uint32_t b_h[4][2], b_l[4][2];
#pragma unroll
            for (int p = 0; p < 2; p++) {
                uint32_t off = SWZ128((uint32_t)((wn + p * 16 + b_row_off) * 128 + k16 * 32 + b_kb));
                uint32_t r0, r1, r2, r3;
                ldmx4(st + SB_HI + off, r0, r1, r2, r3);
                b_h[p * 2][0] = r0; b_h[p * 2][1] = r1;
                b_h[p * 2 + 1][0] = r2; b_h[p * 2 + 1][1] = r3;
                ldmx4(st + SB_LO + off, r0, r1, r2, r3);
                b_l[p * 2][0] = r0; b_l[p * 2][1] = r1;
                b_l[p * 2 + 1][0] = r2; b_l[p * 2 + 1][1] = r3;
            }
#pragma unroll
            for (int mi = 0; mi < 4; mi++)
#pragma unroll
                for (int ni = 0; ni < 4; ni++) {
                    mma_bf16(acc[mi][ni], a_h[mi], b_h[ni]);
                    mma_bf16(acc[mi][ni], a_h[mi], b_l[ni]);
                    mma_bf16(acc[mi][ni], a_l[mi], b_h[ni]);
                }
        }
        __syncthreads();
    }

    // epilogue: c fragment mapping m16n8: c0,c1 -> row=g, col=2t{+1}; c2,c3 -> row=g+8
    int g = lid >> 2;
    int t = lid & 3;
#pragma unroll
    for (int mi = 0; mi < 4; mi++) {
        size_t r0 = block_m + wm + mi * 16 + g;
        size_t r1 = r0 + 8;
#pragma unroll
        for (int ni = 0; ni < 4; ni++) {
            int col = block_n + wn + ni * 8 + t * 2;
            if (r0 < N_NODES)
                *reinterpret_cast<float2*>(out + r0 * OUT_DIM + col) =
                    make_float2(acc[mi][ni][0], acc[mi][ni][1]);
            if (r1 < N_NODES)
                *reinterpret_cast<float2*>(out + r1 * OUT_DIM + col) =
                    make_float2(acc[mi][ni][2], acc[mi][ni][3]);
        }
    }
}

// ---------------------------------------------------------------------------
extern "C" void kernel_launch(void* const* d_in, const int* in_sizes, int n_in,
                              void* d_out, int out_size) {
    const float* feature = (const float*)d_in[0];
    const float* weight  = (const float*)d_in[1];
    const int*   src     = (const int*)d_in[2];
    const int*   dst     = (const int*)d_in[3];
    float* out = (float*)d_out;

    cudaFuncSetAttribute(mma_gemm_kernel,
                         cudaFuncAttributeMaxDynamicSharedMemorySize, SMEM_GEMM);

    // CSR build
    zero_deg_kernel<<<(N_NODES + 255) / 256, 256>>>();
    hist_kernel<<<(N_EDGES + 255) / 256, 256>>>(dst);
    scan_kernel<<<1, 1024>>>();
    fill_kernel<<<(N_EDGES + 255) / 256, 256>>>(src, dst);

    // Weight split
    wsplit_kernel<<<IN_DIM, OUT_DIM>>>(weight);

    // Gather-sum -> bf16 hi/lo  (32 threads/node)
    long long work = (long long)N_PAD * 32;
    gather_kernel<<<(int)((work + 255) / 256), 256>>>(feature);

    // Tensor-core GEMM (HMMA mma.sync, 3-stage cp.async pipeline)
    dim3 ggrid(N_PAD / 128, OUT_DIM / 128);
    mma_gemm_kernel<<<ggrid, 256, SMEM_GEMM>>>(out);
}

// round 11
// speedup vs baseline: 2.7160x; 1.0768x over previous
#include <cuda_runtime.h>
#include <cuda_bf16.h>
#include <cuda_fp16.h>
#include <cstdint>

#define N_NODES 50000
#define N_EDGES 800000
#define IN_DIM 256
#define OUT_DIM 256
#define N_PAD 50048                 // 391 * 128

// ---------------- scratch (device globals; no allocs) ----------------
__device__ __half        g_feat_h[(size_t)N_NODES * IN_DIM];  // 25.6 MB
__device__ __nv_bfloat16 g_agg_hi[(size_t)N_PAD * IN_DIM];    // 25.6 MB
__device__ __nv_bfloat16 g_agg_lo[(size_t)N_PAD * IN_DIM];    // 25.6 MB
__device__ __nv_bfloat16 g_w_hi[IN_DIM * OUT_DIM];            // transposed: [n][k]
__device__ __nv_bfloat16 g_w_lo[IN_DIM * OUT_DIM];
__device__ int g_deg[N_NODES];
__device__ int g_off[N_NODES + 1];
__device__ int g_pos[N_NODES];
__device__ int g_csr_src[N_EDGES];

#define SWZ128(off) ((off) ^ (((off) >> 3) & 0x70))

__device__ __forceinline__ uint32_t smem_u32(const void* p) {
    uint32_t a;
    asm("{ .reg .u64 t; cvta.to.shared.u64 t, %1; cvt.u32.u64 %0, t; }" : "=r"(a) : "l"(p));
    return a;
}

__device__ __forceinline__ void ldmx4(uint32_t addr, uint32_t& r0, uint32_t& r1,
                                      uint32_t& r2, uint32_t& r3) {
    asm volatile("ldmatrix.sync.aligned.m8n8.x4.shared.b16 {%0,%1,%2,%3}, [%4];"
                 : "=r"(r0), "=r"(r1), "=r"(r2), "=r"(r3) : "r"(addr));
}

__device__ __forceinline__ void mma_bf16(float* c, const uint32_t* a, const uint32_t* b) {
    asm volatile(
        "mma.sync.aligned.m16n8k16.row.col.f32.bf16.bf16.f32 "
        "{%0,%1,%2,%3}, {%4,%5,%6,%7}, {%8,%9}, {%0,%1,%2,%3};"
        : "+f"(c[0]), "+f"(c[1]), "+f"(c[2]), "+f"(c[3])
        : "r"(a[0]), "r"(a[1]), "r"(a[2]), "r"(a[3]), "r"(b[0]), "r"(b[1]));
}

__device__ __forceinline__ void cp_async16(uint32_t s, const void* g) {
    asm volatile("cp.async.cg.shared.global [%0], [%1], 16;" :: "r"(s), "l"(g));
}
#define CP_COMMIT() asm volatile("cp.async.commit_group;" ::: "memory")
#define CP_WAIT(n)  asm volatile("cp.async.wait_group %0;" :: "n"(n) : "memory")

// ---------------------------------------------------------------------------
// CSR build
// ---------------------------------------------------------------------------
__global__ void zero_deg_kernel() {
    int i = blockIdx.x * blockDim.x + threadIdx.x;
    if (i < N_NODES) g_deg[i] = 0;
}
__global__ void hist_kernel(const int* __restrict__ dst) {
    int e = blockIdx.x * blockDim.x + threadIdx.x;
    if (e < N_EDGES) atomicAdd(&g_deg[dst[e]], 1);
}
__global__ __launch_bounds__(1024) void scan_kernel() {
    __shared__ int sums[1024];
    int tid = threadIdx.x;
    const int CH = (N_NODES + 1023) / 1024;
    int start = tid * CH;
    int end = start + CH; if (end > N_NODES) end = N_NODES;
    int s = 0;
    for (int i = start; i < end; i++) s += g_deg[i];
    sums[tid] = s;
    __syncthreads();
    for (int off = 1; off < 1024; off <<= 1) {
        int v = (tid >= off) ? sums[tid - off] : 0;
        __syncthreads();
        sums[tid] += v;
        __syncthreads();
    }
    int base = (tid > 0) ? sums[tid - 1] : 0;
    for (int i = start; i < end; i++) {
        g_off[i] = base;
        g_pos[i] = base;
        base += g_deg[i];
    }
    if (tid == 1023) g_off[N_NODES] = base;
}
__global__ void fill_kernel(const int* __restrict__ src, const int* __restrict__ dst) {
    int e = blockIdx.x * blockDim.x + threadIdx.x;
    if (e >= N_EDGES) return;
    int p = atomicAdd(&g_pos[dst[e]], 1);
    g_csr_src[p] = src[e];
}

// ---------------------------------------------------------------------------
// Feature fp32 -> fp16 convert (one pass, 8 elements/thread)
// ---------------------------------------------------------------------------
__global__ void fconv_kernel(const float* __restrict__ feat) {
    size_t i = (size_t)blockIdx.x * blockDim.x + threadIdx.x;   // uint4 (8-half) index
    size_t n8 = (size_t)N_NODES * IN_DIM / 8;
    if (i >= n8) return;
    const float4* fp = reinterpret_cast<const float4*>(feat) + i * 2;
    float4 a = __ldg(fp), b = __ldg(fp + 1);
    __half2 h0 = __floats2half2_rn(a.x, a.y);
    __half2 h1 = __floats2half2_rn(a.z, a.w);
    __half2 h2 = __floats2half2_rn(b.x, b.y);
    __half2 h3 = __floats2half2_rn(b.z, b.w);
    uint4 o;
    o.x = *reinterpret_cast<uint32_t*>(&h0);
    o.y = *reinterpret_cast<uint32_t*>(&h1);
    o.z = *reinterpret_cast<uint32_t*>(&h2);
    o.w = *reinterpret_cast<uint32_t*>(&h3);
    reinterpret_cast<uint4*>(g_feat_h)[i] = o;
}

// ---------------------------------------------------------------------------
// Gather-sum over fp16 features -> bf16 hi/lo split.
// Warp = one node; each thread owns 8 halves (one 16B uint4 per edge row).
// fp32 accumulation; per-warp reads 512B contiguous per edge.
// ---------------------------------------------------------------------------
__device__ __forceinline__ void acc8(float* acc, uint4 v) {
    __half2* h = reinterpret_cast<__half2*>(&v);
#pragma unroll
    for (int j = 0; j < 4; j++) {
        float2 f = __half22float2(h[j]);
        acc[j * 2 + 0] += f.x;
        acc[j * 2 + 1] += f.y;
    }
}

__global__ void gather_kernel() {
    long long id = (long long)blockIdx.x * blockDim.x + threadIdx.x;
    int node = (int)(id >> 5);
    int chunk = (int)(id & 31);            // owns halves [chunk*8, chunk*8+8)
    if (node >= N_PAD) return;

    float acc[8];
#pragma unroll
    for (int j = 0; j < 8; j++) acc[j] = 0.f;

    if (node < N_NODES) {
        int b = g_off[node];
        int e = g_off[node + 1];
        int i = b;
        for (; i + 4 <= e; i += 4) {
            int s0 = __ldg(&g_csr_src[i]);
            int s1 = __ldg(&g_csr_src[i + 1]);
            int s2 = __ldg(&g_csr_src[i + 2]);
            int s3 = __ldg(&g_csr_src[i + 3]);
            uint4 v0 = __ldg(reinterpret_cast<const uint4*>(g_feat_h + (size_t)s0 * IN_DIM) + chunk);
            uint4 v1 = __ldg(reinterpret_cast<const uint4*>(g_feat_h + (size_t)s1 * IN_DIM) + chunk);
            uint4 v2 = __ldg(reinterpret_cast<const uint4*>(g_feat_h + (size_t)s2 * IN_DIM) + chunk);
            uint4 v3 = __ldg(reinterpret_cast<const uint4*>(g_feat_h + (size_t)s3 * IN_DIM) + chunk);
            acc8(acc, v0); acc8(acc, v1); acc8(acc, v2); acc8(acc, v3);
        }
        for (; i < e; i++) {
            int s = __ldg(&g_csr_src[i]);
            acc8(acc, __ldg(reinterpret_cast<const uint4*>(g_feat_h + (size_t)s * IN_DIM) + chunk));
        }
    }

    // split to bf16 hi/lo, one 16B store each
    ushort hv[8], lv[8];
#pragma unroll
    for (int j = 0; j < 8; j++) {
        __nv_bfloat16 h = __float2bfloat16(acc[j]);
        __nv_bfloat16 l = __float2bfloat16(acc[j] - __bfloat162float(h));
        hv[j] = __bfloat16_as_ushort(h);
        lv[j] = __bfloat16_as_ushort(l);
    }
    size_t base = (size_t)node * IN_DIM + chunk * 8;
    *reinterpret_cast<uint4*>(&g_agg_hi[base]) = *reinterpret_cast<uint4*>(hv);
    *reinterpret_cast<uint4*>(&g_agg_lo[base]) = *reinterpret_cast<uint4*>(lv);
}

// ---------------------------------------------------------------------------
// Weight split + transpose: g_w_hi/lo[n][k] = split(W[k][n])
// ---------------------------------------------------------------------------
__global__ void wsplit_kernel(const float* __restrict__ W) {
    int k = blockIdx.x;
    int n = threadIdx.x;
    float x = W[(size_t)k * OUT_DIM + n];
    __nv_bfloat16 h = __float2bfloat16(x);
    __nv_bfloat16 l = __float2bfloat16(x - __bfloat162float(h));
    g_w_hi[(size_t)n * IN_DIM + k] = h;
    g_w_lo[(size_t)n * IN_DIM + k] = l;
}

// ---------------------------------------------------------------------------
// HMMA GEMM with cp.async 3-stage pipeline (unchanged from R10).
// ---------------------------------------------------------------------------
#define KC 64
#define SA_HI 0
#define SA_LO 16384
#define SB_HI 32768
#define SB_LO 49152
#define STAGE_BYTES 65536
#define NSTAGE 3
#define SMEM_GEMM (NSTAGE * STAGE_BYTES)

__global__ __launch_bounds__(256, 1) void mma_gemm_kernel(float* __restrict__ out) {
    extern __shared__ char smem[];
    uint32_t sb = smem_u32(smem);
    int tid = threadIdx.x;
    int wid = tid >> 5;
    int lid = tid & 31;
    size_t block_m = (size_t)blockIdx.x * 128;
    int block_n = blockIdx.y * 128;

    int wm = (wid >> 2) * 64;
    int wn = (wid & 3) * 32;

    const char* ahi = reinterpret_cast<const char*>(g_agg_hi);
    const char* alo = reinterpret_cast<const char*>(g_agg_lo);
    const char* bhi = reinterpret_cast<const char*>(g_w_hi);
    const char* blo = reinterpret_cast<const char*>(g_w_lo);

    float acc[4][4][4];
#pragma unroll
    for (int i = 0; i < 4; i++)
#pragma unroll
        for (int j = 0; j < 4; j++)
#pragma unroll
            for (int q = 0; q < 4; q++) acc[i][j][q] = 0.f;

    int a_row = wm + (lid & 15);
    int a_kb  = (lid >> 4) * 16;
    int bq    = lid >> 3;
    int b_row_off = (bq >> 1) * 8 + (lid & 7);
    int b_kb  = (bq & 1) * 16;

    auto load_chunk = [&](int c, int st) {
        int k0 = c * KC;
        uint32_t base = sb + st * STAGE_BYTES;
#pragma unroll
        for (int it = 0; it < 4; it++) {
            int idx = tid + it * 256;
            int row = idx >> 3, q = idx & 7;
            uint32_t doff = SWZ128((uint32_t)(row * 128 + q * 16));
            size_t ab = (((block_m + row) * IN_DIM + k0) << 1) + (q << 4);
            cp_async16(base + SA_HI + doff, ahi + ab);
            cp_async16(base + SA_LO + doff, alo + ab);
            size_t bb = ((((size_t)(block_n + row)) * IN_DIM + k0) << 1) + (q << 4);
            cp_async16(base + SB_HI + doff, bhi + bb);
            cp_async16(base + SB_LO + doff, blo + bb);
        }
        CP_COMMIT();
    };

    load_chunk(0, 0);
    load_chunk(1, 1);

    for (int c = 0; c < 4; c++) {
        if (c < 2) {
            load_chunk(c + 2, (c + 2) % NSTAGE);
            CP_WAIT(2);
        } else if (c == 2) {
            CP_WAIT(1);
        } else {
            CP_WAIT(0);
        }
        __syncthreads();

        uint32_t st = sb + (c % NSTAGE) * STAGE_BYTES;
#pragma unroll
        for (int k16 = 0; k16 < 4; k16++) {
            uint32_t a_h[4][4], a_l[4][4];
#pragma unroll
            for (int mi = 0; mi < 4; mi++) {
                uint32_t off = SWZ128((uint32_t)((a_row + mi * 16) * 128 + k16 * 32 + a_kb));
                ldmx4(st + SA_HI + off, a_h[mi][0], a_h[mi][1], a_h[mi][2], a_h[mi][3]);
                ldmx4(st + SA_LO + off, a_l[mi][0], a_l[mi][1], a_l[mi][2], a_l[mi][3]);
            }
            uint32_t b_h[4][2], b_l[4][2];
#pragma unroll
            for (int p = 0; p < 2; p++) {
                uint32_t off = SWZ128((uint32_t)((wn + p * 16 + b_row_off) * 128 + k16 * 32 + b_kb));
                uint32_t r0, r1, r2, r3;
                ldmx4(st + SB_HI + off, r0, r1, r2, r3);
                b_h[p * 2][0] = r0; b_h[p * 2][1] = r1;
                b_h[p * 2 + 1][0] = r2; b_h[p * 2 + 1][1] = r3;
                ldmx4(st + SB_LO + off, r0, r1, r2, r3);
                b_l[p * 2][0] = r0; b_l[p * 2][1] = r1;
                b_l[p * 2 + 1][0] = r2; b_l[p * 2 + 1][1] = r3;
            }
#pragma unroll
            for (int mi = 0; mi < 4; mi++)
#pragma unroll
                for (int ni = 0; ni < 4; ni++) {
                    mma_bf16(acc[mi][ni], a_h[mi], b_h[ni]);
                    mma_bf16(acc[mi][ni], a_h[mi], b_l[ni]);
                    mma_bf16(acc[mi][ni], a_l[mi], b_h[ni]);
                }
        }
        __syncthreads();
    }

    int g = lid >> 2;
    int t = lid & 3;
#pragma unroll
    for (int mi = 0; mi < 4; mi++) {
        size_t r0 = block_m + wm + mi * 16 + g;
        size_t r1 = r0 + 8;
#pragma unroll
        for (int ni = 0; ni < 4; ni++) {
            int col = block_n + wn + ni * 8 + t * 2;
            if (r0 < N_NODES)
                *reinterpret_cast<float2*>(out + r0 * OUT_DIM + col) =
                    make_float2(acc[mi][ni][0], acc[mi][ni][1]);
            if (r1 < N_NODES)
                *reinterpret_cast<float2*>(out + r1 * OUT_DIM + col) =
                    make_float2(acc[mi][ni][2], acc[mi][ni][3]);
        }
    }
}

// ---------------------------------------------------------------------------
extern "C" void kernel_launch(void* const* d_in, const int* in_sizes, int n_in,
                              void* d_out, int out_size) {
    const float* feature = (const float*)d_in[0];
    const float* weight  = (const float*)d_in[1];
    const int*   src     = (const int*)d_in[2];
    const int*   dst     = (const int*)d_in[3];
    float* out = (float*)d_out;

    cudaFuncSetAttribute(mma_gemm_kernel,
                         cudaFuncAttributeMaxDynamicSharedMemorySize, SMEM_GEMM);

    // CSR build
    zero_deg_kernel<<<(N_NODES + 255) / 256, 256>>>();
    hist_kernel<<<(N_EDGES + 255) / 256, 256>>>(dst);
    scan_kernel<<<1, 1024>>>();
    fill_kernel<<<(N_EDGES + 255) / 256, 256>>>(src, dst);

    // Feature fp32 -> fp16 (independent of CSR)
    long long n8 = (long long)N_NODES * IN_DIM / 8;
    fconv_kernel<<<(int)((n8 + 255) / 256), 256>>>(feature);

    // Weight split
    wsplit_kernel<<<IN_DIM, OUT_DIM>>>(weight);

    // Gather-sum over fp16 features -> bf16 hi/lo
    long long work = (long long)N_PAD * 32;
    gather_kernel<<<(int)((work + 255) / 256), 256>>>();

    // Tensor-core GEMM (HMMA mma.sync, 3-stage cp.async pipeline)
    dim3 ggrid(N_PAD / 128, OUT_DIM / 128);
    mma_gemm_kernel<<<ggrid, 256, SMEM_GEMM>>>(out);
}

// round 14
// speedup vs baseline: 2.7350x; 1.0070x over previous
#include <cuda_runtime.h>
#include <cuda_bf16.h>
#include <cuda_fp16.h>
#include <cstdint>

#define N_NODES 50000
#define N_EDGES 800000
#define IN_DIM 256
#define OUT_DIM 256
#define N_PAD 50048                 // 391 * 128

// ---------------- scratch (device globals; no allocs) ----------------
__device__ __half        g_feat_h[(size_t)N_NODES * IN_DIM];  // 25.6 MB
__device__ __nv_bfloat16 g_agg_hi[(size_t)N_PAD * IN_DIM];    // 25.6 MB
__device__ __nv_bfloat16 g_agg_lo[(size_t)N_PAD * IN_DIM];    // 25.6 MB
__device__ __nv_bfloat16 g_w_hi[IN_DIM * OUT_DIM];            // transposed: [n][k]
__device__ __nv_bfloat16 g_w_lo[IN_DIM * OUT_DIM];
__device__ int g_deg[N_NODES + 32];     // padded so int4 ops are safe
__device__ int g_off[N_NODES + 1];
__device__ int g_pos[N_NODES];
__device__ int g_csr_src[N_EDGES];

#define SWZ128(off) ((off) ^ (((off) >> 3) & 0x70))

__device__ __forceinline__ uint32_t smem_u32(const void* p) {
    uint32_t a;
    asm("{ .reg .u64 t; cvta.to.shared.u64 t, %1; cvt.u32.u64 %0, t; }" : "=r"(a) : "l"(p));
    return a;
}

__device__ __forceinline__ void ldmx4(uint32_t addr, uint32_t& r0, uint32_t& r1,
                                      uint32_t& r2, uint32_t& r3) {
    asm volatile("ldmatrix.sync.aligned.m8n8.x4.shared.b16 {%0,%1,%2,%3}, [%4];"
                 : "=r"(r0), "=r"(r1), "=r"(r2), "=r"(r3) : "r"(addr));
}

__device__ __forceinline__ void mma_bf16(float* c, const uint32_t* a, const uint32_t* b) {
    asm volatile(
        "mma.sync.aligned.m16n8k16.row.col.f32.bf16.bf16.f32 "
        "{%0,%1,%2,%3}, {%4,%5,%6,%7}, {%8,%9}, {%0,%1,%2,%3};"
        : "+f"(c[0]), "+f"(c[1]), "+f"(c[2]), "+f"(c[3])
        : "r"(a[0]), "r"(a[1]), "r"(a[2]), "r"(a[3]), "r"(b[0]), "r"(b[1]));
}

__device__ __forceinline__ void cp_async16(uint32_t s, const void* g) {
    asm volatile("cp.async.cg.shared.global [%0], [%1], 16;" :: "r"(s), "l"(g));
}
#define CP_COMMIT() asm volatile("cp.async.commit_group;" ::: "memory")
#define CP_WAIT(n)  asm volatile("cp.async.wait_group %0;" :: "n"(n) : "memory")

// ---------------------------------------------------------------------------
// CSR build (all edge kernels unrolled x4: 4 independent mem chains/thread)
// ---------------------------------------------------------------------------
__global__ void zero_deg_kernel() {
    int i = blockIdx.x * blockDim.x + threadIdx.x;   // int4 index
    if (i < (N_NODES + 3) / 4)
        reinterpret_cast<int4*>(g_deg)[i] = make_int4(0, 0, 0, 0);
}
__global__ void hist_kernel(const int* __restrict__ dst) {
    int t = blockIdx.x * blockDim.x + threadIdx.x;
    int e = t * 4;
    if (e >= N_EDGES) return;
    int4 d = *reinterpret_cast<const int4*>(dst + e);
    atomicAdd(&g_deg[d.x], 1);
    atomicAdd(&g_deg[d.y], 1);
    atomicAdd(&g_deg[d.z], 1);
    atomicAdd(&g_deg[d.w], 1);
}
__global__ __launch_bounds__(1024) void scan_kernel() {
    __shared__ int sums[1024];
    int tid = threadIdx.x;
    const int CH = (N_NODES + 1023) / 1024;
    int start = tid * CH;
    int end = start + CH; if (end > N_NODES) end = N_NODES;
    int s = 0;
    for (int i = start; i < end; i++) s += g_deg[i];
    sums[tid] = s;
    __syncthreads();
    for (int off = 1; off < 1024; off <<= 1) {
        int v = (tid >= off) ? sums[tid - off] : 0;
        __syncthreads();
        sums[tid] += v;
        __syncthreads();
    }
    int base = (tid > 0) ? sums[tid - 1] : 0;
    for (int i = start; i < end; i++) {
        g_off[i] = base;
        g_pos[i] = base;
        base += g_deg[i];
    }
    if (tid == 1023) g_off[N_NODES] = base;
}
__global__ void fill_kernel(const int* __restrict__ src, const int* __restrict__ dst) {
    int t = blockIdx.x * blockDim.x + threadIdx.x;
    int e = t * 4;
    if (e >= N_EDGES) return;
    int4 d = *reinterpret_cast<const int4*>(dst + e);
    int4 s = *reinterpret_cast<const int4*>(src + e);
    int p0 = atomicAdd(&g_pos[d.x], 1);
    int p1 = atomicAdd(&g_pos[d.y], 1);
    int p2 = atomicAdd(&g_pos[d.z], 1);
    int p3 = atomicAdd(&g_pos[d.w], 1);
    g_csr_src[p0] = s.x;
    g_csr_src[p1] = s.y;
    g_csr_src[p2] = s.z;
    g_csr_src[p3] = s.w;
}

// ---------------------------------------------------------------------------
// Feature fp32 -> fp16 convert
// ---------------------------------------------------------------------------
__global__ void fconv_kernel(const float* __restrict__ feat) {
    size_t i = (size_t)blockIdx.x * blockDim.x + threadIdx.x;   // uint4 (8-half) index
    size_t n8 = (size_t)N_NODES * IN_DIM / 8;
    if (i >= n8) return;
    const float4* fp = reinterpret_cast<const float4*>(feat) + i * 2;
    float4 a = __ldg(fp), b = __ldg(fp + 1);
    __half2 h0 = __floats2half2_rn(a.x, a.y);
    __half2 h1 = __floats2half2_rn(a.z, a.w);
    __half2 h2 = __floats2half2_rn(b.x, b.y);
    __half2 h3 = __floats2half2_rn(b.z, b.w);
    uint4 o;
    o.x = *reinterpret_cast<uint32_t*>(&h0);
    o.y = *reinterpret_cast<uint32_t*>(&h1);
    o.z = *reinterpret_cast<uint32_t*>(&h2);
    o.w = *reinterpret_cast<uint32_t*>(&h3);
    reinterpret_cast<uint4*>(g_feat_h)[i] = o;
}

// ---------------------------------------------------------------------------
// Gather-sum over fp16 features -> bf16 hi/lo split (unchanged from R11)
// ---------------------------------------------------------------------------
__device__ __forceinline__ void acc8(float* acc, uint4 v) {
    __half2* h = reinterpret_cast<__half2*>(&v);
#pragma unroll
    for (int j = 0; j < 4; j++) {
        float2 f = __half22float2(h[j]);
        acc[j * 2 + 0] += f.x;
        acc[j * 2 + 1] += f.y;
    }
}

__global__ void gather_kernel() {
    long long id = (long long)blockIdx.x * blockDim.x + threadIdx.x;
    int node = (int)(id >> 5);
    int chunk = (int)(id & 31);
    if (node >= N_PAD) return;

    float acc[8];
#pragma unroll
    for (int j = 0; j < 8; j++) acc[j] = 0.f;

    if (node < N_NODES) {
        int b = g_off[node];
        int e = g_off[node + 1];
        int i = b;
        for (; i + 4 <= e; i += 4) {
            int s0 = __ldg(&g_csr_src[i]);
            int s1 = __ldg(&g_csr_src[i + 1]);
            int s2 = __ldg(&g_csr_src[i + 2]);
            int s3 = __ldg(&g_csr_src[i + 3]);
            uint4 v0 = __ldg(reinterpret_cast<const uint4*>(g_feat_h + (size_t)s0 * IN_DIM) + chunk);
            uint4 v1 = __ldg(reinterpret_cast<const uint4*>(g_feat_h + (size_t)s1 * IN_DIM) + chunk);
            uint4 v2 = __ldg(reinterpret_cast<const uint4*>(g_feat_h + (size_t)s2 * IN_DIM) + chunk);
            uint4 v3 = __ldg(reinterpret_cast<const uint4*>(g_feat_h + (size_t)s3 * IN_DIM) + chunk);
            acc8(acc, v0); acc8(acc, v1); acc8(acc, v2); acc8(acc, v3);
        }
        for (; i < e; i++) {
            int s = __ldg(&g_csr_src[i]);
            acc8(acc, __ldg(reinterpret_cast<const uint4*>(g_feat_h + (size_t)s * IN_DIM) + chunk));
        }
    }

    ushort hv[8], lv[8];
#pragma unroll
    for (int j = 0; j < 8; j++) {
        __nv_bfloat16 h = __float2bfloat16(acc[j]);
        __nv_bfloat16 l = __float2bfloat16(acc[j] - __bfloat162float(h));
        hv[j] = __bfloat16_as_ushort(h);
        lv[j] = __bfloat16_as_ushort(l);
    }
    size_t base = (size_t)node * IN_DIM + chunk * 8;
    *reinterpret_cast<uint4*>(&g_agg_hi[base]) = *reinterpret_cast<uint4*>(hv);
    *reinterpret_cast<uint4*>(&g_agg_lo[base]) = *reinterpret_cast<uint4*>(lv);
}

// ---------------------------------------------------------------------------
// Weight split + transpose
// ---------------------------------------------------------------------------
__global__ void wsplit_kernel(const float* __restrict__ W) {
    int k = blockIdx.x;
    int n = threadIdx.x;
    float x = W[(size_t)k * OUT_DIM + n];
    __nv_bfloat16 h = __float2bfloat16(x);
    __nv_bfloat16 l = __float2bfloat16(x - __bfloat162float(h));
    g_w_hi[(size_t)n * IN_DIM + k] = h;
    g_w_lo[(size_t)n * IN_DIM + k] = l;
}

// ---------------------------------------------------------------------------
// HMMA GEMM v2: 128x256 CTA tile (full N), 8 warps, warp tile 64x64.
// 3-MMA bf16 split, 2-stage cp.async pipeline, 96KB/stage (192KB total).
// ---------------------------------------------------------------------------
#define KC 64
#define SA_HI 0
#define SA_LO 16384
#define SB_HI 32768
#define SB_LO 65536
#define STAGE_BYTES 98304
#define SMEM_GEMM (2 * STAGE_BYTES)

__global__ __launch_bounds__(256, 1) void mma_gemm_kernel(float* __restrict__ out) {
    extern __shared__ char smem[];
    uint32_t sb = smem_u32(smem);
    int tid = threadIdx.x;
    int wid = tid >> 5;
    int lid = tid & 31;
    size_t block_m = (size_t)blockIdx.x * 128;

    int wm = (wid >> 2) * 64;     // 0 or 64
    int wn = (wid & 3) * 64;      // 0,64,128,192

    const char* ahi = reinterpret_cast<const char*>(g_agg_hi);
    const char* alo = reinterpret_cast<const char*>(g_agg_lo);
    const char* bhi = reinterpret_cast<const char*>(g_w_hi);
    const char* blo = reinterpret_cast<const char*>(g_w_lo);

    float acc[4][8][4];
#pragma unroll
    for (int i = 0; i < 4; i++)
#pragma unroll
        for (int j = 0; j < 8; j++)
#pragma unroll
            for (int q = 0; q < 4; q++) acc[i][j][q] = 0.f;

    int a_row = wm + (lid & 15);
    int a_kb  = (lid >> 4) * 16;
    int bq    = lid >> 3;
    int b_row_off = (bq >> 1) * 8 + (lid & 7);
    int b_kb  = (bq & 1) * 16;

    auto load_chunk = [&](int c, int st) {
        int k0 = c * KC;
        uint32_t base = sb + st * STAGE_BYTES;
#pragma unroll
        for (int it = 0; it < 4; it++) {
            int idx = tid + it * 256;          // 0..1023: A rows 0..127
            int row = idx >> 3, q = idx & 7;
            uint32_t doff = SWZ128((uint32_t)(row * 128 + q * 16));
            size_t ab = (((block_m + row) * IN_DIM + k0) << 1) + (q << 4);
            cp_async16(base + SA_HI + doff, ahi + ab);
            cp_async16(base + SA_LO + doff, alo + ab);
        }
#pragma unroll
        for (int it = 0; it < 8; it++) {
            int idx = tid + it * 256;          // 0..2047: B rows 0..255
            int row = idx >> 3, q = idx & 7;
            uint32_t doff = SWZ128((uint32_t)(row * 128 + q * 16));
            size_t bb = (((size_t)row * IN_DIM + k0) << 1) + (q << 4);
            cp_async16(base + SB_HI + doff, bhi + bb);
            cp_async16(base + SB_LO + doff, blo + bb);
        }
        CP_COMMIT();
    };

    load_chunk(0, 0);

    for (int c = 0; c < 4; c++) {
        if (c < 3) {
            load_chunk(c + 1, (c + 1) & 1);
            CP_WAIT(1);
        } else {
            CP_WAIT(0);
        }
        __syncthreads();

        uint32_t st = sb + (c & 1) * STAGE_BYTES;
#pragma unroll
        for (int k16 = 0; k16 < 4; k16++) {
            uint32_t a_h[4][4], a_l[4][4];
#pragma unroll
            for (int mi = 0; mi < 4; mi++) {
                uint32_t off = SWZ128((uint32_t)((a_row + mi * 16) * 128 + k16 * 32 + a_kb));
                ldmx4(st + SA_HI + off, a_h[mi][0], a_h[mi][1], a_h[mi][2], a_h[mi][3]);
                ldmx4(st + SA_LO + off, a_l[mi][0], a_l[mi][1], a_l[mi][2], a_l[mi][3]);
            }
            uint32_t b_h[8][2], b_l[8][2];
#pragma unroll
            for (int p = 0; p < 4; p++) {
                uint32_t off = SWZ128((uint32_t)((wn + p * 16 + b_row_off) * 128 + k16 * 32 + b_kb));
                uint32_t r0, r1, r2, r3;
                ldmx4(st + SB_HI + off, r0, r1, r2, r3);
                b_h[p * 2][0] = r0; b_h[p * 2][1] = r1;
                b_h[p * 2 + 1][0] = r2; b_h[p * 2 + 1][1] = r3;
                ldmx4(st + SB_LO + off, r0, r1, r2, r3);
                b_l[p * 2][0] = r0; b_l[p * 2][1] = r1;
                b_l[p * 2 + 1][0] = r2; b_l[p * 2 + 1][1] = r3;
            }
#pragma unroll
            for (int mi = 0; mi < 4; mi++)
#pragma unroll
                for (int ni = 0; ni < 8; ni++) {
                    mma_bf16(acc[mi][ni], a_h[mi], b_h[ni]);
                    mma_bf16(acc[mi][ni], a_h[mi], b_l[ni]);
                    mma_bf16(acc[mi][ni], a_l[mi], b_h[ni]);
                }
        }
        __syncthreads();
    }

    int g = lid >> 2;
    int t = lid & 3;
#pragma unroll
    for (int mi = 0; mi < 4; mi++) {
        size_t r0 = block_m + wm + mi * 16 + g;
        size_t r1 = r0 + 8;
#pragma unroll
        for (int ni = 0; ni < 8; ni++) {
            int col = wn + ni * 8 + t * 2;
            if (r0 < N_NODES)
                *reinterpret_cast<float2*>(out + r0 * OUT_DIM + col) =
                    make_float2(acc[mi][ni][0], acc[mi][ni][1]);
            if (r1 < N_NODES)
                *reinterpret_cast<float2*>(out + r1 * OUT_DIM + col) =
                    make_float2(acc[mi][ni][2], acc[mi][ni][3]);
        }
    }
}

// ---------------------------------------------------------------------------
extern "C" void kernel_launch(void* const* d_in, const int* in_sizes, int n_in,
                              void* d_out, int out_size) {
    const float* feature = (const float*)d_in[0];
    const float* weight  = (const float*)d_in[1];
    const int*   src     = (const int*)d_in[2];
    const int*   dst     = (const int*)d_in[3];
    float* out = (float*)d_out;

    cudaFuncSetAttribute(mma_gemm_kernel,
                         cudaFuncAttributeMaxDynamicSharedMemorySize, SMEM_GEMM);

    // CSR build (x4 unrolled edge kernels)
    zero_deg_kernel<<<(N_NODES / 4 + 255) / 256, 256>>>();
    hist_kernel<<<(N_EDGES / 4 + 255) / 256, 256>>>(dst);
    scan_kernel<<<1, 1024>>>();
    fill_kernel<<<(N_EDGES / 4 + 255) / 256, 256>>>(src, dst);

    // Feature fp32 -> fp16
    long long n8 = (long long)N_NODES * IN_DIM / 8;
    fconv_kernel<<<(int)((n8 + 255) / 256), 256>>>(feature);

    // Weight split
    wsplit_kernel<<<IN_DIM, OUT_DIM>>>(weight);

    // Gather-sum -> bf16 hi/lo
    long long work = (long long)N_PAD * 32;
    gather_kernel<<<(int)((work + 255) / 256), 256>>>();

    // Tensor-core GEMM (full-N tile)
    mma_gemm_kernel<<<N_PAD / 128, 256, SMEM_GEMM>>>(out);
}

// round 15
// speedup vs baseline: 2.9820x; 1.0903x over previous
#include <cuda_runtime.h>
#include <cuda_bf16.h>
#include <cuda_fp16.h>
#include <cstdint>

#define N_NODES 50000
#define N_EDGES 800000
#define IN_DIM 256
#define OUT_DIM 256
#define N_PAD 50048                 // 391 * 128

// ---------------- scratch (device globals; no allocs) ----------------
__device__ __half g_feat_h[(size_t)N_NODES * IN_DIM];   // 25.6 MB
__device__ __half g_agg[(size_t)N_PAD * IN_DIM];        // 25.6 MB (fp16 agg)
__device__ __half g_w_hi[IN_DIM * OUT_DIM];             // transposed: [n][k]
__device__ __half g_w_lo[IN_DIM * OUT_DIM];
__device__ int g_deg[N_NODES + 32];
__device__ int g_off[N_NODES + 1];
__device__ int g_pos[N_NODES];
__device__ int g_csr_src[N_EDGES];

#define SWZ128(off) ((off) ^ (((off) >> 3) & 0x70))

__device__ __forceinline__ uint32_t smem_u32(const void* p) {
    uint32_t a;
    asm("{ .reg .u64 t; cvta.to.shared.u64 t, %1; cvt.u32.u64 %0, t; }" : "=r"(a) : "l"(p));
    return a;
}

__device__ __forceinline__ void ldmx4(uint32_t addr, uint32_t& r0, uint32_t& r1,
                                      uint32_t& r2, uint32_t& r3) {
    asm volatile("ldmatrix.sync.aligned.m8n8.x4.shared.b16 {%0,%1,%2,%3}, [%4];"
                 : "=r"(r0), "=r"(r1), "=r"(r2), "=r"(r3) : "r"(addr));
}

__device__ __forceinline__ void mma_f16(float* c, const uint32_t* a, const uint32_t* b) {
    asm volatile(
        "mma.sync.aligned.m16n8k16.row.col.f32.f16.f16.f32 "
        "{%0,%1,%2,%3}, {%4,%5,%6,%7}, {%8,%9}, {%0,%1,%2,%3};"
        : "+f"(c[0]), "+f"(c[1]), "+f"(c[2]), "+f"(c[3])
        : "r"(a[0]), "r"(a[1]), "r"(a[2]), "r"(a[3]), "r"(b[0]), "r"(b[1]));
}

__device__ __forceinline__ void cp_async16(uint32_t s, const void* g) {
    asm volatile("cp.async.cg.shared.global [%0], [%1], 16;" :: "r"(s), "l"(g));
}
#define CP_COMMIT() asm volatile("cp.async.commit_group;" ::: "memory")
#define CP_WAIT(n)  asm volatile("cp.async.wait_group %0;" :: "n"(n) : "memory")

__device__ __forceinline__ void red_add(int* addr, int v) {
    asm volatile("red.global.add.s32 [%0], %1;" :: "l"(addr), "r"(v) : "memory");
}

// ---------------------------------------------------------------------------
// CSR build
// ---------------------------------------------------------------------------
__global__ void zero_deg_kernel() {
    int i = blockIdx.x * blockDim.x + threadIdx.x;
    if (i < (N_NODES + 3) / 4)
        reinterpret_cast<int4*>(g_deg)[i] = make_int4(0, 0, 0, 0);
}
__global__ void hist_kernel(const int* __restrict__ dst) {
    int t = blockIdx.x * blockDim.x + threadIdx.x;
    int e = t * 4;
    if (e >= N_EDGES) return;
    int4 d = *reinterpret_cast<const int4*>(dst + e);
    red_add(&g_deg[d.x], 1);
    red_add(&g_deg[d.y], 1);
    red_add(&g_deg[d.z], 1);
    red_add(&g_deg[d.w], 1);
}
__global__ __launch_bounds__(1024) void scan_kernel() {
    __shared__ int sums[1024];
    int tid = threadIdx.x;
    const int CH = (N_NODES + 1023) / 1024;
    int start = tid * CH;
    int end = start + CH; if (end > N_NODES) end = N_NODES;
    int s = 0;
    for (int i = start; i < end; i++) s += g_deg[i];
    sums[tid] = s;
    __syncthreads();
    for (int off = 1; off < 1024; off <<= 1) {
        int v = (tid >= off) ? sums[tid - off] : 0;
        __syncthreads();
        sums[tid] += v;
        __syncthreads();
    }
    int base = (tid > 0) ? sums[tid - 1] : 0;
    for (int i = start; i < end; i++) {
        g_off[i] = base;
        g_pos[i] = base;
        base += g_deg[i];
    }
    if (tid == 1023) g_off[N_NODES] = base;
}
__global__ void fill_kernel(const int* __restrict__ src, const int* __restrict__ dst) {
    int t = blockIdx.x * blockDim.x + threadIdx.x;
    int e = t * 4;
    if (e >= N_EDGES) return;
    int4 d = *reinterpret_cast<const int4*>(dst + e);
    int4 s = *reinterpret_cast<const int4*>(src + e);
    int p0 = atomicAdd(&g_pos[d.x], 1);
    int p1 = atomicAdd(&g_pos[d.y], 1);
    int p2 = atomicAdd(&g_pos[d.z], 1);
    int p3 = atomicAdd(&g_pos[d.w], 1);
    g_csr_src[p0] = s.x;
    g_csr_src[p1] = s.y;
    g_csr_src[p2] = s.z;
    g_csr_src[p3] = s.w;
}

// ---------------------------------------------------------------------------
// Feature fp32 -> fp16 convert
// ---------------------------------------------------------------------------
__global__ void fconv_kernel(const float* __restrict__ feat) {
    size_t i = (size_t)blockIdx.x * blockDim.x + threadIdx.x;
    size_t n8 = (size_t)N_NODES * IN_DIM / 8;
    if (i >= n8) return;
    const float4* fp = reinterpret_cast<const float4*>(feat) + i * 2;
    float4 a = __ldg(fp), b = __ldg(fp + 1);
    __half2 h0 = __floats2half2_rn(a.x, a.y);
    __half2 h1 = __floats2half2_rn(a.z, a.w);
    __half2 h2 = __floats2half2_rn(b.x, b.y);
    __half2 h3 = __floats2half2_rn(b.z, b.w);
    uint4 o;
    o.x = *reinterpret_cast<uint32_t*>(&h0);
    o.y = *reinterpret_cast<uint32_t*>(&h1);
    o.z = *reinterpret_cast<uint32_t*>(&h2);
    o.w = *reinterpret_cast<uint32_t*>(&h3);
    reinterpret_cast<uint4*>(g_feat_h)[i] = o;
}

// ---------------------------------------------------------------------------
// Gather-sum over fp16 features -> fp16 agg (single buffer)
// ---------------------------------------------------------------------------
__device__ __forceinline__ void acc8(float* acc, uint4 v) {
    __half2* h = reinterpret_cast<__half2*>(&v);
#pragma unroll
    for (int j = 0; j < 4; j++) {
        float2 f = __half22float2(h[j]);
        acc[j * 2 + 0] += f.x;
        acc[j * 2 + 1] += f.y;
    }
}

__global__ void gather_kernel() {
    long long id = (long long)blockIdx.x * blockDim.x + threadIdx.x;
    int node = (int)(id >> 5);
    int chunk = (int)(id & 31);
    if (node >= N_PAD) return;

    float acc[8];
#pragma unroll
    for (int j = 0; j < 8; j++) acc[j] = 0.f;

    if (node < N_NODES) {
        int b = g_off[node];
        int e = g_off[node + 1];
        int i = b;
        for (; i + 4 <= e; i += 4) {
            int s0 = __ldg(&g_csr_src[i]);
            int s1 = __ldg(&g_csr_src[i + 1]);
            int s2 = __ldg(&g_csr_src[i + 2]);
            int s3 = __ldg(&g_csr_src[i + 3]);
            uint4 v0 = __ldg(reinterpret_cast<const uint4*>(g_feat_h + (size_t)s0 * IN_DIM) + chunk);
            uint4 v1 = __ldg(reinterpret_cast<const uint4*>(g_feat_h + (size_t)s1 * IN_DIM) + chunk);
            uint4 v2 = __ldg(reinterpret_cast<const uint4*>(g_feat_h + (size_t)s2 * IN_DIM) + chunk);
            uint4 v3 = __ldg(reinterpret_cast<const uint4*>(g_feat_h + (size_t)s3 * IN_DIM) + chunk);
            acc8(acc, v0); acc8(acc, v1); acc8(acc, v2); acc8(acc, v3);
        }
        for (; i < e; i++) {
            int s = __ldg(&g_csr_src[i]);
            acc8(acc, __ldg(reinterpret_cast<const uint4*>(g_feat_h + (size_t)s * IN_DIM) + chunk));
        }
    }

    __half2 o0 = __floats2half2_rn(acc[0], acc[1]);
    __half2 o1 = __floats2half2_rn(acc[2], acc[3]);
    __half2 o2 = __floats2half2_rn(acc[4], acc[5]);
    __half2 o3 = __floats2half2_rn(acc[6], acc[7]);
    uint4 o;
    o.x = *reinterpret_cast<uint32_t*>(&o0);
    o.y = *reinterpret_cast<uint32_t*>(&o1);
    o.z = *reinterpret_cast<uint32_t*>(&o2);
    o.w = *reinterpret_cast<uint32_t*>(&o3);
    size_t base = (size_t)node * IN_DIM + chunk * 8;
    *reinterpret_cast<uint4*>(&g_agg[base]) = o;
}

// ---------------------------------------------------------------------------
// Weight fp16 2-term split + transpose: W[k][n] -> hi/lo fp16 at [n][k]
// ---------------------------------------------------------------------------
__global__ void wsplit_kernel(const float* __restrict__ W) {
    int k = blockIdx.x;
    int n = threadIdx.x;
    float x = W[(size_t)k * OUT_DIM + n];
    __half h = __float2half_rn(x);
    __half l = __float2half_rn(x - __half2float(h));
    g_w_hi[(size_t)n * IN_DIM + k] = h;
    g_w_lo[(size_t)n * IN_DIM + k] = l;
}

// ---------------------------------------------------------------------------
// HMMA GEMM: out = A_fp16 @ (Whi + Wlo)^T, 2-MMA fp16 split.
// 128x256 CTA tile, 8 warps, warp tile 64x64, K chunk 64.
// Stage = A 16KB + Bhi 32KB + Blo 32KB = 80KB; 2 stages = 160KB.
// ---------------------------------------------------------------------------
#define KC 64
#define SA   0
#define SB_HI 16384
#define SB_LO 49152
#define STAGE_BYTES 81920
#define SMEM_GEMM (2 * STAGE_BYTES)

__global__ __launch_bounds__(256, 1) void mma_gemm_kernel(float* __restrict__ out) {
    extern __shared__ char smem[];
    uint32_t sb = smem_u32(smem);
    int tid = threadIdx.x;
    int wid = tid >> 5;
    int lid = tid & 31;
    size_t block_m = (size_t)blockIdx.x * 128;

    int wm = (wid >> 2) * 64;     // 0 or 64
    int wn = (wid & 3) * 64;      // 0,64,128,192

    const char* ag  = reinterpret_cast<const char*>(g_agg);
    const char* bhi = reinterpret_cast<const char*>(g_w_hi);
    const char* blo = reinterpret_cast<const char*>(g_w_lo);

    float acc[4][8][4];
#pragma unroll
    for (int i = 0; i < 4; i++)
#pragma unroll
        for (int j = 0; j < 8; j++)
#pragma unroll
            for (int q = 0; q < 4; q++) acc[i][j][q] = 0.f;

    int a_row = wm + (lid & 15);
    int a_kb  = (lid >> 4) * 16;
    int bq    = lid >> 3;
    int b_row_off = (bq >> 1) * 8 + (lid & 7);
    int b_kb  = (bq & 1) * 16;

    auto load_chunk = [&](int c, int st) {
        int k0 = c * KC;
        uint32_t base = sb + st * STAGE_BYTES;
#pragma unroll
        for (int it = 0; it < 4; it++) {
            int idx = tid + it * 256;          // A: 128 rows x 8 x 16B
            int row = idx >> 3, q = idx & 7;
            uint32_t doff = SWZ128((uint32_t)(row * 128 + q * 16));
            size_t ab = (((block_m + row) * IN_DIM + k0) << 1) + (q << 4);
            cp_async16(base + SA + doff, ag + ab);
        }
#pragma unroll
        for (int it = 0; it < 8; it++) {
            int idx = tid + it * 256;          // B: 256 rows x 8 x 16B
            int row = idx >> 3, q = idx & 7;
            uint32_t doff = SWZ128((uint32_t)(row * 128 + q * 16));
            size_t bb = (((size_t)row * IN_DIM + k0) << 1) + (q << 4);
            cp_async16(base + SB_HI + doff, bhi + bb);
            cp_async16(base + SB_LO + doff, blo + bb);
        }
        CP_COMMIT();
    };

    load_chunk(0, 0);

    for (int c = 0; c < 4; c++) {
        if (c < 3) {
            load_chunk(c + 1, (c + 1) & 1);
            CP_WAIT(1);
        } else {
            CP_WAIT(0);
        }
        __syncthreads();

        uint32_t st = sb + (c & 1) * STAGE_BYTES;
#pragma unroll
        for (int k16 = 0; k16 < 4; k16++) {
            uint32_t a_f[4][4];
#pragma unroll
            for (int mi = 0; mi < 4; mi++) {
                uint32_t off = SWZ128((uint32_t)((a_row + mi * 16) * 128 + k16 * 32 + a_kb));
                ldmx4(st + SA + off, a_f[mi][0], a_f[mi][1], a_f[mi][2], a_f[mi][3]);
            }
            uint32_t b_h[8][2], b_l[8][2];
#pragma unroll
            for (int p = 0; p < 4; p++) {
                uint32_t off = SWZ128((uint32_t)((wn + p * 16 + b_row_off) * 128 + k16 * 32 + b_kb));
                uint32_t r0, r1, r2, r3;
                ldmx4(st + SB_HI + off, r0, r1, r2, r3);
                b_h[p * 2][0] = r0; b_h[p * 2][1] = r1;
                b_h[p * 2 + 1][0] = r2; b_h[p * 2 + 1][1] = r3;
                ldmx4(st + SB_LO + off, r0, r1, r2, r3);
                b_l[p * 2][0] = r0; b_l[p * 2][1] = r1;
                b_l[p * 2 + 1][0] = r2; b_l[p * 2 + 1][1] = r3;
            }
#pragma unroll
            for (int mi = 0; mi < 4; mi++)
#pragma unroll
                for (int ni = 0; ni < 8; ni++) {
                    mma_f16(acc[mi][ni], a_f[mi], b_h[ni]);
                    mma_f16(acc[mi][ni], a_f[mi], b_l[ni]);
                }
        }
        __syncthreads();
    }

    int g = lid >> 2;
    int t = lid & 3;
#pragma unroll
    for (int mi = 0; mi < 4; mi++) {
        size_t r0 = block_m + wm + mi * 16 + g;
        size_t r1 = r0 + 8;
#pragma unroll
        for (int ni = 0; ni < 8; ni++) {
            int col = wn + ni * 8 + t * 2;
            if (r0 < N_NODES)
                *reinterpret_cast<float2*>(out + r0 * OUT_DIM + col) =
                    make_float2(acc[mi][ni][0], acc[mi][ni][1]);
            if (r1 < N_NODES)
                *reinterpret_cast<float2*>(out + r1 * OUT_DIM + col) =
                    make_float2(acc[mi][ni][2], acc[mi][ni][3]);
        }
    }
}

// ---------------------------------------------------------------------------
extern "C" void kernel_launch(void* const* d_in, const int* in_sizes, int n_in,
                              void* d_out, int out_size) {
    const float* feature = (const float*)d_in[0];
    const float* weight  = (const float*)d_in[1];
    const int*   src     = (const int*)d_in[2];
    const int*   dst     = (const int*)d_in[3];
    float* out = (float*)d_out;

    cudaFuncSetAttribute(mma_gemm_kernel,
                         cudaFuncAttributeMaxDynamicSharedMemorySize, SMEM_GEMM);

    // CSR build
    zero_deg_kernel<<<(N_NODES / 4 + 255) / 256, 256>>>();
    hist_kernel<<<(N_EDGES / 4 + 255) / 256, 256>>>(dst);
    scan_kernel<<<1, 1024>>>();
    fill_kernel<<<(N_EDGES / 4 + 255) / 256, 256>>>(src, dst);

    // Feature fp32 -> fp16
    long long n8 = (long long)N_NODES * IN_DIM / 8;
    fconv_kernel<<<(int)((n8 + 255) / 256), 256>>>(feature);

    // Weight fp16 hi/lo split
    wsplit_kernel<<<IN_DIM, OUT_DIM>>>(weight);

    // Gather-sum -> fp16 agg
    long long work = (long long)N_PAD * 32;
    gather_kernel<<<(int)((work + 255) / 256), 256>>>();

    // Tensor-core GEMM (fp16 A, 2-MMA W split)
    mma_gemm_kernel<<<N_PAD / 128, 256, SMEM_GEMM>>>(out);
}